// round 12
// baseline (speedup 1.0000x reference)
#include <cuda_runtime.h>
#include <cuda_bf16.h>
#include <math.h>
#include <stdint.h>

#define VV 32000
#define DD 1024
#define LL 6
#define HH 16
#define FFD 4096
#define SS 1024
#define BB 2
#define DK 64
#define MM (BB*SS)   // 2048 rows

// ---------------- gemm tile config (BN=128, 3-stage) ----------------
#define BMT 128
#define BNT 128
#define KC 64
#define AT_BYTES (BMT*128)
#define WT_BYTES (BNT*128)
#define STAGE_BYTES (2*AT_BYTES + 2*WT_BYTES)   // 65536
#define GSMEM_TOTAL (3*STAGE_BYTES)             // 196608

// ---------------- BIG gemm config (BN=256, 2-stage) ----------------
#define BWT_BYTES (256*128)
#define BSTAGE (2*AT_BYTES + 2*BWT_BYTES)       // 98304
#define BSMEM_TOTAL (2*BSTAGE)                  // 196608

// ---------------- attention smem layout ----------------
#define AQ_H 0
#define AQ_L 8192
#define AK_H 16384
#define AK_L 24576
#define AV_H 32768
#define AV_L 40960
#define ATT_SMEM 49152

// ---------------- whole-model weight split offsets (elements) ----------------
#define OFF_WQ ((size_t)0)
#define OFF_WK ((size_t)6*DD*DD)
#define OFF_WV ((size_t)12*DD*DD)
#define OFF_WO ((size_t)18*DD*DD)
#define OFF_W1 ((size_t)24*DD*DD)
#define OFF_W2 ((size_t)24*DD*DD + (size_t)6*FFD*DD)
#define WTOT   ((size_t)24*DD*DD + (size_t)12*FFD*DD)

// ---------------- scratch ----------------
__device__ float g_h[MM*DD];
__device__ __nv_bfloat16 g_qh[MM*DD];
__device__ __nv_bfloat16 g_ql[MM*DD];
__device__ __nv_bfloat16 g_kh[MM*DD];
__device__ __nv_bfloat16 g_kl[MM*DD];
__device__ __nv_bfloat16 g_vh[MM*DD];
__device__ __nv_bfloat16 g_vl[MM*DD];
__device__ __nv_bfloat16 g_ah[MM*DD];
__device__ __nv_bfloat16 g_al[MM*DD];
__device__ __nv_bfloat16 g_bh[MM*FFD];
__device__ __nv_bfloat16 g_bl[MM*FFD];
__device__ __nv_bfloat16 g_wh[WTOT];
__device__ __nv_bfloat16 g_wl[WTOT];
__device__ __nv_bfloat16 g_eh[VV*DD];
__device__ __nv_bfloat16 g_el[VV*DD];

// ---------------- side stream + events (created once, before any capture) ----------------
struct SideStream {
    cudaStream_t s2;
    cudaEvent_t ev0, ev1, ev2;
    SideStream() {
        cudaStreamCreate(&s2);
        cudaEventCreateWithFlags(&ev0, cudaEventDisableTiming);
        cudaEventCreateWithFlags(&ev1, cudaEventDisableTiming);
        cudaEventCreateWithFlags(&ev2, cudaEventDisableTiming);
    }
};
static SideStream g_ss;

// ---------------- helpers ----------------
__device__ __forceinline__ uint32_t smem_u32(const void* p) {
    uint32_t a;
    asm("{ .reg .u64 t; cvta.to.shared.u64 t, %1; cvt.u32.u64 %0, t; }" : "=r"(a) : "l"(p));
    return a;
}
__device__ __forceinline__ float gelu_f(float x) {
    return 0.5f * x * (1.0f + erff(x * 0.70710678118654752f));
}
__device__ __forceinline__ void cp16(uint32_t dst, const void* src) {
    asm volatile("cp.async.cg.shared.global [%0], [%1], 16;" :: "r"(dst), "l"(src));
}
__device__ __forceinline__ void ldmatrix4(uint32_t* r, uint32_t addr) {
    asm volatile("ldmatrix.sync.aligned.m8n8.x4.shared.b16 {%0,%1,%2,%3}, [%4];"
                 : "=r"(r[0]), "=r"(r[1]), "=r"(r[2]), "=r"(r[3]) : "r"(addr));
}
__device__ __forceinline__ void ldmatrix4t(uint32_t* r, uint32_t addr) {
    asm volatile("ldmatrix.sync.aligned.m8n8.x4.trans.shared.b16 {%0,%1,%2,%3}, [%4];"
                 : "=r"(r[0]), "=r"(r[1]), "=r"(r[2]), "=r"(r[3]) : "r"(addr));
}
__device__ __forceinline__ void mma16816(float* c, const uint32_t* a, uint32_t b0, uint32_t b1) {
    asm volatile("mma.sync.aligned.m16n8k16.row.col.f32.bf16.bf16.f32 "
                 "{%0,%1,%2,%3}, {%4,%5,%6,%7}, {%8,%9}, {%0,%1,%2,%3};"
                 : "+f"(c[0]), "+f"(c[1]), "+f"(c[2]), "+f"(c[3])
                 : "r"(a[0]), "r"(a[1]), "r"(a[2]), "r"(a[3]), "r"(b0), "r"(b1));
}
__device__ __forceinline__ __nv_bfloat162 split_hi2(float a, float b) {
    __nv_bfloat162 r; r.x = __float2bfloat16(a); r.y = __float2bfloat16(b); return r;
}
__device__ __forceinline__ __nv_bfloat162 split_lo2(float a, float b, __nv_bfloat162 h) {
    __nv_bfloat162 r;
    r.x = __float2bfloat16(a - __bfloat162float(h.x));
    r.y = __float2bfloat16(b - __bfloat162float(h.y));
    return r;
}
__device__ __forceinline__ uint32_t swzoff(int row, int cu) {
    return (uint32_t)(row * 128 + ((cu * 16) ^ ((row & 7) * 16)));
}

// ---------------- fp32 -> (bf16 hi, bf16 lo) split, 4 elems/thread ----------------
__global__ void split_kernel(const float* __restrict__ x,
                             __nv_bfloat16* __restrict__ h,
                             __nv_bfloat16* __restrict__ l) {
    int i = blockIdx.x * blockDim.x + threadIdx.x;
    float4 v = ((const float4*)x)[i];
    __nv_bfloat162 h0 = split_hi2(v.x, v.y);
    __nv_bfloat162 h1 = split_hi2(v.z, v.w);
    __nv_bfloat162 l0 = split_lo2(v.x, v.y, h0);
    __nv_bfloat162 l1 = split_lo2(v.z, v.w, h1);
    ((__nv_bfloat162*)h)[2*i]   = h0;
    ((__nv_bfloat162*)h)[2*i+1] = h1;
    ((__nv_bfloat162*)l)[2*i]   = l0;
    ((__nv_bfloat162*)l)[2*i+1] = l1;
}

// ---------------- shared GEMM param struct ----------------
struct GParams {
    const __nv_bfloat16 *Ah, *Al;
    const __nv_bfloat16 *Wh[3], *Wl[3];
    const float *bias[3];
    const float *res[3];
    float *C[3];
    __nv_bfloat16 *Ch[3], *Cl[3];
    int K, N, act;
};

__device__ __forceinline__ void ldA(uint32_t* r, uint32_t base, int r0, int kbyte, int lane) {
    int row = r0 + (lane & 15);
    int x = ((lane >> 4) * 16 + kbyte) ^ ((row & 7) * 16);
    ldmatrix4(r, base + row * 128 + x);
}
__device__ __forceinline__ void ldB(uint32_t* r, uint32_t base, int nb, int kbyte, int lane) {
    int nrow = nb + (lane & 7) + ((lane >> 4) << 3);
    int x = (((lane >> 3) & 1) * 16 + kbyte) ^ ((nrow & 7) * 16);
    ldmatrix4(r, base + nrow * 128 + x);
}
__device__ __forceinline__ void ldBt(uint32_t* r, uint32_t base, int nb, int kr0, int lane) {
    int row = kr0 + (lane & 7) + (((lane >> 3) & 1) << 3);
    int colb = nb * 2 + ((lane >> 4) << 4);
    int x = colb ^ ((row & 7) * 16);
    ldmatrix4t(r, base + row * 128 + x);
}

__device__ __forceinline__ void epi_frag(int act, const float* bias, const float* res,
        float* C, __nv_bfloat16* Ch, __nv_bfloat16* Cl,
        float a0, float a1, float a2, float a3,
        int row0, int row1, int col, int N) {
    float v00 = a0, v01 = a1, v10 = a2, v11 = a3;
    if (bias) {
        float2 b2 = *(const float2*)(bias + col);
        v00 += b2.x; v01 += b2.y; v10 += b2.x; v11 += b2.y;
    }
    if (res) {
        float2 r0 = *(const float2*)(res + (size_t)row0 * N + col);
        float2 r1 = *(const float2*)(res + (size_t)row1 * N + col);
        v00 += r0.x; v01 += r0.y; v10 += r1.x; v11 += r1.y;
    }
    if (act) {
        v00 = gelu_f(v00); v01 = gelu_f(v01);
        v10 = gelu_f(v10); v11 = gelu_f(v11);
    }
    if (Ch) {
        __nv_bfloat162 H0 = split_hi2(v00, v01);
        __nv_bfloat162 H1 = split_hi2(v10, v11);
        __nv_bfloat162 L0 = split_lo2(v00, v01, H0);
        __nv_bfloat162 L1 = split_lo2(v10, v11, H1);
        *(__nv_bfloat162*)(Ch + (size_t)row0 * N + col) = H0;
        *(__nv_bfloat162*)(Cl + (size_t)row0 * N + col) = L0;
        *(__nv_bfloat162*)(Ch + (size_t)row1 * N + col) = H1;
        *(__nv_bfloat162*)(Cl + (size_t)row1 * N + col) = L1;
    } else {
        *(float2*)(C + (size_t)row0 * N + col) = make_float2(v00, v01);
        *(float2*)(C + (size_t)row1 * N + col) = make_float2(v10, v11);
    }
}

// ---------------- 3-stage GEMM (BN=128) ----------------
__device__ __forceinline__ void stage_loads(uint32_t sstage,
        const __nv_bfloat16* Ah, const __nv_bfloat16* Al,
        const __nv_bfloat16* Wh, const __nv_bfloat16* Wl,
        int m0, int n0, int k0, int K, int tid) {
    #pragma unroll
    for (int t = 0; t < 4; t++) {
        int u = tid + (t << 8);
        int row = u >> 3, cu = u & 7;
        cp16(sstage + swzoff(row, cu), Ah + (size_t)(m0 + row) * K + k0 + cu * 8);
    }
    #pragma unroll
    for (int t = 0; t < 4; t++) {
        int u = tid + (t << 8);
        int row = u >> 3, cu = u & 7;
        cp16(sstage + AT_BYTES + swzoff(row, cu), Al + (size_t)(m0 + row) * K + k0 + cu * 8);
    }
    #pragma unroll
    for (int t = 0; t < 4; t++) {
        int u = tid + (t << 8);
        int row = u >> 3, cu = u & 7;
        cp16(sstage + 2*AT_BYTES + swzoff(row, cu), Wh + (size_t)(n0 + row) * K + k0 + cu * 8);
    }
    #pragma unroll
    for (int t = 0; t < 4; t++) {
        int u = tid + (t << 8);
        int row = u >> 3, cu = u & 7;
        cp16(sstage + 2*AT_BYTES + WT_BYTES + swzoff(row, cu), Wl + (size_t)(n0 + row) * K + k0 + cu * 8);
    }
    asm volatile("cp.async.commit_group;" ::: "memory");
}

__global__ void __launch_bounds__(256, 1) gemm_bf16_kernel(GParams p) {
    extern __shared__ char smem[];
    const int tid = threadIdx.x;
    const int wid = tid >> 5, lane = tid & 31;
    const int z = blockIdx.z;
    const int m0 = blockIdx.y * BMT, n0 = blockIdx.x * BNT;
    const int K = p.K, N = p.N;
    const __nv_bfloat16* Wh = p.Wh[z];
    const __nv_bfloat16* Wl = p.Wl[z];
    const float* bias = p.bias[z];
    const float* res = p.res[z];
    float* C = p.C[z];
    __nv_bfloat16* Ch = p.Ch[z];
    __nv_bfloat16* Cl = p.Cl[z];
    const uint32_t sb = smem_u32(smem);

    const int wm = (wid >> 1) * 32;
    const int wn = (wid & 1) * 64;

    float acc[2][8][4];
    #pragma unroll
    for (int i = 0; i < 2; i++)
        #pragma unroll
        for (int j = 0; j < 8; j++)
            #pragma unroll
            for (int q = 0; q < 4; q++) acc[i][j][q] = 0.0f;

    const int nch = K / KC;
    stage_loads(sb,                 p.Ah, p.Al, Wh, Wl, m0, n0, 0,    K, tid);
    stage_loads(sb +   STAGE_BYTES, p.Ah, p.Al, Wh, Wl, m0, n0, KC,   K, tid);
    stage_loads(sb + 2*STAGE_BYTES, p.Ah, p.Al, Wh, Wl, m0, n0, 2*KC, K, tid);

    for (int i = 0; i < nch; i++) {
        asm volatile("cp.async.wait_group 2;" ::: "memory");
        __syncthreads();
        uint32_t st = sb + (uint32_t)(i % 3) * STAGE_BYTES;
        uint32_t aH = st, aL = st + AT_BYTES;
        uint32_t wH = st + 2*AT_BYTES, wL = st + 2*AT_BYTES + WT_BYTES;

        #pragma unroll
        for (int ks = 0; ks < 4; ks++) {
            const int kbyte = ks * 32;
            uint32_t ah0[4], ah1[4], al0[4], al1[4];
            ldA(ah0, aH, wm,      kbyte, lane);
            ldA(ah1, aH, wm + 16, kbyte, lane);
            ldA(al0, aL, wm,      kbyte, lane);
            ldA(al1, aL, wm + 16, kbyte, lane);
            uint32_t bh[4][4], bl[4][4];
            #pragma unroll
            for (int g = 0; g < 4; g++) {
                ldB(bh[g], wH, wn + g * 16, kbyte, lane);
                ldB(bl[g], wL, wn + g * 16, kbyte, lane);
            }
            #pragma unroll
            for (int g = 0; g < 4; g++) {
                #pragma unroll
                for (int s = 0; s < 2; s++) {
                    int nj = g * 2 + s;
                    uint32_t h0 = bh[g][s*2], h1 = bh[g][s*2+1];
                    uint32_t l0 = bl[g][s*2], l1 = bl[g][s*2+1];
                    mma16816(acc[0][nj], ah0, h0, h1);
                    mma16816(acc[1][nj], ah1, h0, h1);
                    mma16816(acc[0][nj], al0, h0, h1);
                    mma16816(acc[1][nj], al1, h0, h1);
                    mma16816(acc[0][nj], ah0, l0, l1);
                    mma16816(acc[1][nj], ah1, l0, l1);
                }
            }
        }
        __syncthreads();
        if (i + 3 < nch)
            stage_loads(st, p.Ah, p.Al, Wh, Wl, m0, n0, (i + 3) * KC, K, tid);
    }

    const int lrow = lane >> 2;
    const int lcol = (lane & 3) * 2;
    #pragma unroll
    for (int mi = 0; mi < 2; mi++) {
        int row0 = m0 + wm + mi * 16 + lrow;
        int row1 = row0 + 8;
        #pragma unroll
        for (int nj = 0; nj < 8; nj++) {
            int col = n0 + wn + nj * 8 + lcol;
            epi_frag(p.act, bias, res, C, Ch, Cl, acc[mi][nj][0], acc[mi][nj][1],
                     acc[mi][nj][2], acc[mi][nj][3], row0, row1, col, N);
        }
    }
}

// ---------------- BIG GEMM: 128x256 CTA, 64x64 warp tiles, 2-stage ----------------
// Grid mapping: blockIdx.x = m-tile (fast), blockIdx.y = n-tile (slow) so the
// 16 CTAs sharing one weight tile are consecutively scheduled (L2 reuse of W).
__device__ __forceinline__ void stage_loads_big(uint32_t sstage,
        const __nv_bfloat16* Ah, const __nv_bfloat16* Al,
        const __nv_bfloat16* Wh, const __nv_bfloat16* Wl,
        int m0, int n0, int k0, int K, int tid) {
    #pragma unroll
    for (int t = 0; t < 4; t++) {
        int u = tid + (t << 8);
        int row = u >> 3, cu = u & 7;
        cp16(sstage + swzoff(row, cu), Ah + (size_t)(m0 + row) * K + k0 + cu * 8);
    }
    #pragma unroll
    for (int t = 0; t < 4; t++) {
        int u = tid + (t << 8);
        int row = u >> 3, cu = u & 7;
        cp16(sstage + AT_BYTES + swzoff(row, cu), Al + (size_t)(m0 + row) * K + k0 + cu * 8);
    }
    #pragma unroll
    for (int t = 0; t < 8; t++) {
        int u = tid + (t << 8);
        int row = u >> 3, cu = u & 7;
        cp16(sstage + 2*AT_BYTES + swzoff(row, cu), Wh + (size_t)(n0 + row) * K + k0 + cu * 8);
    }
    #pragma unroll
    for (int t = 0; t < 8; t++) {
        int u = tid + (t << 8);
        int row = u >> 3, cu = u & 7;
        cp16(sstage + 2*AT_BYTES + BWT_BYTES + swzoff(row, cu), Wl + (size_t)(n0 + row) * K + k0 + cu * 8);
    }
    asm volatile("cp.async.commit_group;" ::: "memory");
}

__global__ void __launch_bounds__(256, 1) gemm_big_kernel(GParams p) {
    extern __shared__ char smem[];
    const int tid = threadIdx.x;
    const int wid = tid >> 5, lane = tid & 31;
    const int m0 = blockIdx.x * BMT, n0 = blockIdx.y * 256;   // swapped mapping
    const int K = p.K, N = p.N;
    const __nv_bfloat16* Wh = p.Wh[0];
    const __nv_bfloat16* Wl = p.Wl[0];
    const float* bias = p.bias[0];
    const float* res = p.res[0];
    float* C = p.C[0];
    __nv_bfloat16* Ch = p.Ch[0];
    __nv_bfloat16* Cl = p.Cl[0];
    const uint32_t sb = smem_u32(smem);

    const int wm = (wid >> 2) * 64;
    const int wn = (wid & 3) * 64;

    float acc[4][8][4];
    #pragma unroll
    for (int m = 0; m < 4; m++)
        #pragma unroll
        for (int j = 0; j < 8; j++)
            #pragma unroll
            for (int q = 0; q < 4; q++) acc[m][j][q] = 0.0f;

    const int nch = K / KC;
    stage_loads_big(sb,          p.Ah, p.Al, Wh, Wl, m0, n0, 0,  K, tid);
    stage_loads_big(sb + BSTAGE, p.Ah, p.Al, Wh, Wl, m0, n0, KC, K, tid);

    for (int i = 0; i < nch; i++) {
        asm volatile("cp.async.wait_group 1;" ::: "memory");
        __syncthreads();
        const uint32_t st = sb + (uint32_t)(i & 1) * BSTAGE;
        const uint32_t aH = st, aL = st + AT_BYTES;
        const uint32_t wH = st + 2*AT_BYTES, wL = st + 2*AT_BYTES + BWT_BYTES;

        #pragma unroll
        for (int ks = 0; ks < 4; ks++) {
            const int kbyte = ks * 32;
            uint32_t ah[4][4], al[4][4];
            #pragma unroll
            for (int m = 0; m < 4; m++) {
                ldA(ah[m], aH, wm + m * 16, kbyte, lane);
                ldA(al[m], aL, wm + m * 16, kbyte, lane);
            }
            #pragma unroll
            for (int g = 0; g < 4; g++) {
                uint32_t bh4[4], bl4[4];
                ldB(bh4, wH, wn + g * 16, kbyte, lane);
                ldB(bl4, wL, wn + g * 16, kbyte, lane);
                #pragma unroll
                for (int s = 0; s < 2; s++) {
                    int nj = g * 2 + s;
                    uint32_t h0 = bh4[s*2], h1 = bh4[s*2+1];
                    uint32_t l0 = bl4[s*2], l1 = bl4[s*2+1];
                    #pragma unroll
                    for (int m = 0; m < 4; m++) {
                        mma16816(acc[m][nj], ah[m], h0, h1);
                        mma16816(acc[m][nj], al[m], h0, h1);
                        mma16816(acc[m][nj], ah[m], l0, l1);
                    }
                }
            }
        }
        __syncthreads();
        if (i + 2 < nch)
            stage_loads_big(st, p.Ah, p.Al, Wh, Wl, m0, n0, (i + 2) * KC, K, tid);
    }

    const int lrow = lane >> 2;
    const int lcol = (lane & 3) * 2;
    #pragma unroll
    for (int m = 0; m < 4; m++) {
        int row0 = m0 + wm + m * 16 + lrow;
        int row1 = row0 + 8;
        #pragma unroll
        for (int nj = 0; nj < 8; nj++) {
            int col = n0 + wn + nj * 8 + lcol;
            epi_frag(p.act, bias, res, C, Ch, Cl, acc[m][nj][0], acc[m][nj][1],
                     acc[m][nj][2], acc[m][nj][3], row0, row1, col, N);
        }
    }
}

// ---------------- embedding + positional encoding ----------------
__global__ void embed_kernel(const int* __restrict__ x, const float* __restrict__ emb,
                             float* __restrict__ h) {
    int idx = blockIdx.x * blockDim.x + threadIdx.x;
    int d  = idx & (DD - 1);
    int bs = idx >> 10;
    int s  = bs & (SS - 1);
    int tok = x[bs];
    int i2 = d & ~1;
    float div = expf(-(float)i2 * (logf(10000.0f) / (float)DD));
    float ang = (float)s * div;
    float pe = (d & 1) ? cosf(ang) : sinf(ang);
    h[idx] = emb[(size_t)tok * DD + d] * 32.0f + pe;
}

// ---------------- layernorm (writes bf16 hi/lo split) ----------------
__global__ void __launch_bounds__(256) ln_kernel(const float* __restrict__ in,
                                                 const float* __restrict__ w,
                                                 const float* __restrict__ b,
                                                 __nv_bfloat16* __restrict__ oh,
                                                 __nv_bfloat16* __restrict__ ol) {
    int row = blockIdx.x;
    int t = threadIdx.x;
    int lane = t & 31, wid = t >> 5;
    __shared__ float red[8];

    float4 x4 = ((const float4*)(in + (size_t)row * DD))[t];
    float s = x4.x + x4.y + x4.z + x4.w;
    #pragma unroll
    for (int o = 16; o; o >>= 1) s += __shfl_xor_sync(0xffffffffu, s, o);
    if (lane == 0) red[wid] = s;
    __syncthreads();
    float tot = red[0]+red[1]+red[2]+red[3]+red[4]+red[5]+red[6]+red[7];
    float mean = tot * (1.0f / DD);
    __syncthreads();

    float d0 = x4.x - mean, d1 = x4.y - mean, d2 = x4.z - mean, d3 = x4.w - mean;
    float vs = d0*d0 + d1*d1 + d2*d2 + d3*d3;
    #pragma unroll
    for (int o = 16; o; o >>= 1) vs += __shfl_xor_sync(0xffffffffu, vs, o);
    if (lane == 0) red[wid] = vs;
    __syncthreads();
    float var = (red[0]+red[1]+red[2]+red[3]+red[4]+red[5]+red[6]+red[7]) * (1.0f / DD);
    float inv = rsqrtf(var + 1e-5f);

    float4 w4 = ((const float4*)w)[t];
    float4 b4 = ((const float4*)b)[t];
    float o0 = d0 * inv * w4.x + b4.x;
    float o1 = d1 * inv * w4.y + b4.y;
    float o2 = d2 * inv * w4.z + b4.z;
    float o3 = d3 * inv * w4.w + b4.w;
    __nv_bfloat162 H0 = split_hi2(o0, o1), H1 = split_hi2(o2, o3);
    __nv_bfloat162 L0 = split_lo2(o0, o1, H0), L1 = split_lo2(o2, o3, H1);
    ((__nv_bfloat162*)(oh + (size_t)row * DD))[2*t]   = H0;
    ((__nv_bfloat162*)(oh + (size_t)row * DD))[2*t+1] = H1;
    ((__nv_bfloat162*)(ol + (size_t)row * DD))[2*t]   = L0;
    ((__nv_bfloat162*)(ol + (size_t)row * DD))[2*t+1] = L1;
}

// ---------------- tensor-core flash attention (R8 proven) ----------------
__device__ __forceinline__ void att_stage(uint32_t dst, const __nv_bfloat16* src,
                                          size_t gbase, int tid) {
    #pragma unroll
    for (int t = 0; t < 4; t++) {
        int u = tid + t * 128;
        int row = u >> 3, cu = u & 7;
        cp16(dst + swzoff(row, cu), src + gbase + (size_t)row * DD + cu * 8);
    }
}

__global__ void __launch_bounds__(128) attn_kernel(
        const __nv_bfloat16* __restrict__ qh, const __nv_bfloat16* __restrict__ ql,
        const __nv_bfloat16* __restrict__ kh, const __nv_bfloat16* __restrict__ kl,
        const __nv_bfloat16* __restrict__ vh, const __nv_bfloat16* __restrict__ vl,
        __nv_bfloat16* __restrict__ ch, __nv_bfloat16* __restrict__ cl) {
    extern __shared__ char asmem[];
    const uint32_t sb = smem_u32(asmem);
    const int qt = blockIdx.x;
    const int bh = blockIdx.y;
    const int hh = bh & (HH - 1);
    const int bb = bh >> 4;
    const int q0 = qt * 64;

    const int tid = threadIdx.x;
    const int wid = tid >> 5, lane = tid & 31;
    const int wq = wid * 16;

    const size_t qbase = (size_t)(bb * SS + q0) * DD + hh * DK;
    att_stage(sb + AQ_H, qh, qbase, tid);
    att_stage(sb + AQ_L, ql, qbase, tid);
    asm volatile("cp.async.commit_group;" ::: "memory");

    float m0 = -1e30f, m1 = -1e30f, l0s = 0.0f, l1s = 0.0f;
    float ctx[8][4];
    #pragma unroll
    for (int j = 0; j < 8; j++)
        #pragma unroll
        for (int e = 0; e < 4; e++) ctx[j][e] = 0.0f;

    const int r = lane >> 2;
    const int cb = (lane & 3) * 2;

    const int ntiles = qt + 1;
    for (int t = 0; t < ntiles; t++) {
        __syncthreads();
        const size_t kbase = (size_t)(bb * SS + t * 64) * DD + hh * DK;
        att_stage(sb + AK_H, kh, kbase, tid);
        att_stage(sb + AK_L, kl, kbase, tid);
        att_stage(sb + AV_H, vh, kbase, tid);
        att_stage(sb + AV_L, vl, kbase, tid);
        asm volatile("cp.async.commit_group;" ::: "memory");
        asm volatile("cp.async.wait_group 0;" ::: "memory");
        __syncthreads();

        float sc[8][4];
        #pragma unroll
        for (int j = 0; j < 8; j++)
            #pragma unroll
            for (int e = 0; e < 4; e++) sc[j][e] = 0.0f;

        #pragma unroll
        for (int ks = 0; ks < 4; ks++) {
            const int kb = ks * 32;
            uint32_t qhf[4], qlf[4];
            ldA(qhf, sb + AQ_H, wq, kb, lane);
            ldA(qlf, sb + AQ_L, wq, kb, lane);
            #pragma unroll
            for (int g = 0; g < 4; g++) {
                uint32_t khf[4], klf[4];
                ldB(khf, sb + AK_H, g * 16, kb, lane);
                ldB(klf, sb + AK_L, g * 16, kb, lane);
                #pragma unroll
                for (int s = 0; s < 2; s++) {
                    int nj = g * 2 + s;
                    mma16816(sc[nj], qhf, khf[s*2], khf[s*2+1]);
                    mma16816(sc[nj], qlf, khf[s*2], khf[s*2+1]);
                    mma16816(sc[nj], qhf, klf[s*2], klf[s*2+1]);
                }
            }
        }
        #pragma unroll
        for (int nj = 0; nj < 8; nj++) {
            sc[nj][0] *= 0.125f; sc[nj][1] *= 0.125f;
            sc[nj][2] *= 0.125f; sc[nj][3] *= 0.125f;
        }

        if (t == qt) {
            #pragma unroll
            for (int nj = 0; nj < 8; nj++) {
                int c0 = nj * 8 + cb;
                if (c0     > wq + r)     sc[nj][0] = -1e30f;
                if (c0 + 1 > wq + r)     sc[nj][1] = -1e30f;
                if (c0     > wq + r + 8) sc[nj][2] = -1e30f;
                if (c0 + 1 > wq + r + 8) sc[nj][3] = -1e30f;
            }
        }

        float tm0 = -1e30f, tm1 = -1e30f;
        #pragma unroll
        for (int nj = 0; nj < 8; nj++) {
            tm0 = fmaxf(tm0, fmaxf(sc[nj][0], sc[nj][1]));
            tm1 = fmaxf(tm1, fmaxf(sc[nj][2], sc[nj][3]));
        }
        tm0 = fmaxf(tm0, __shfl_xor_sync(0xffffffffu, tm0, 1));
        tm0 = fmaxf(tm0, __shfl_xor_sync(0xffffffffu, tm0, 2));
        tm1 = fmaxf(tm1, __shfl_xor_sync(0xffffffffu, tm1, 1));
        tm1 = fmaxf(tm1, __shfl_xor_sync(0xffffffffu, tm1, 2));
        float m0n = fmaxf(m0, tm0), m1n = fmaxf(m1, tm1);
        float a0 = __expf(m0 - m0n), a1 = __expf(m1 - m1n);
        float sum0 = 0.0f, sum1 = 0.0f;
        #pragma unroll
        for (int nj = 0; nj < 8; nj++) {
            sc[nj][0] = __expf(sc[nj][0] - m0n);
            sc[nj][1] = __expf(sc[nj][1] - m0n);
            sc[nj][2] = __expf(sc[nj][2] - m1n);
            sc[nj][3] = __expf(sc[nj][3] - m1n);
            sum0 += sc[nj][0] + sc[nj][1];
            sum1 += sc[nj][2] + sc[nj][3];
        }
        sum0 += __shfl_xor_sync(0xffffffffu, sum0, 1);
        sum0 += __shfl_xor_sync(0xffffffffu, sum0, 2);
        sum1 += __shfl_xor_sync(0xffffffffu, sum1, 1);
        sum1 += __shfl_xor_sync(0xffffffffu, sum1, 2);
        l0s = l0s * a0 + sum0;
        l1s = l1s * a1 + sum1;
        m0 = m0n; m1 = m1n;
        #pragma unroll
        for (int nj = 0; nj < 8; nj++) {
            ctx[nj][0] *= a0; ctx[nj][1] *= a0;
            ctx[nj][2] *= a1; ctx[nj][3] *= a1;
        }

        #pragma unroll
        for (int ks = 0; ks < 4; ks++) {
            uint32_t ph[4], pl[4];
            {
                __nv_bfloat162 t0 = split_hi2(sc[2*ks][0],   sc[2*ks][1]);
                __nv_bfloat162 t1 = split_hi2(sc[2*ks][2],   sc[2*ks][3]);
                __nv_bfloat162 t2 = split_hi2(sc[2*ks+1][0], sc[2*ks+1][1]);
                __nv_bfloat162 t3 = split_hi2(sc[2*ks+1][2], sc[2*ks+1][3]);
                ph[0] = *(uint32_t*)&t0; ph[1] = *(uint32_t*)&t1;
                ph[2] = *(uint32_t*)&t2; ph[3] = *(uint32_t*)&t3;
                __nv_bfloat162 u0 = split_lo2(sc[2*ks][0],   sc[2*ks][1],   t0);
                __nv_bfloat162 u1 = split_lo2(sc[2*ks][2],   sc[2*ks][3],   t1);
                __nv_bfloat162 u2 = split_lo2(sc[2*ks+1][0], sc[2*ks+1][1], t2);
                __nv_bfloat162 u3 = split_lo2(sc[2*ks+1][2], sc[2*ks+1][3], t3);
                pl[0] = *(uint32_t*)&u0; pl[1] = *(uint32_t*)&u1;
                pl[2] = *(uint32_t*)&u2; pl[3] = *(uint32_t*)&u3;
            }
            const int kr0 = ks * 16;
            #pragma unroll
            for (int g = 0; g < 4; g++) {
                uint32_t vhf[4], vlf[4];
                ldBt(vhf, sb + AV_H, g * 16, kr0, lane);
                ldBt(vlf, sb + AV_L, g * 16, kr0, lane);
                #pragma unroll
                for (int s = 0; s < 2; s++) {
                    int nj = g * 2 + s;
                    mma16816(ctx[nj], ph, vhf[s*2], vhf[s*2+1]);
                    mma16816(ctx[nj], ph, vlf[s*2], vlf[s*2+1]);
                    mma16816(ctx[nj], pl, vhf[s*2], vhf[s*2+1]);
                }
            }
        }
    }

    float i0 = 1.0f / l0s, i1 = 1.0f / l1s;
    size_t row0 = (size_t)(bb * SS + q0 + wq + r) * DD + hh * DK;
    size_t row1 = row0 + (size_t)8 * DD;
    #pragma unroll
    for (int nj = 0; nj < 8; nj++) {
        int d = nj * 8 + cb;
        float x0 = ctx[nj][0] * i0, x1 = ctx[nj][1] * i0;
        __nv_bfloat162 H = split_hi2(x0, x1);
        __nv_bfloat162 L = split_lo2(x0, x1, H);
        *(__nv_bfloat162*)(ch + row0 + d) = H;
        *(__nv_bfloat162*)(cl + row0 + d) = L;
        float y0 = ctx[nj][2] * i1, y1 = ctx[nj][3] * i1;
        __nv_bfloat162 H1 = split_hi2(y0, y1);
        __nv_bfloat162 L1 = split_lo2(y0, y1, H1);
        *(__nv_bfloat162*)(ch + row1 + d) = H1;
        *(__nv_bfloat162*)(cl + row1 + d) = L1;
    }
}

// ---------------- host-side launch helpers ----------------
static void launch_split_s(const float* x, __nv_bfloat16* h, __nv_bfloat16* l,
                           size_t n, cudaStream_t s) {
    split_kernel<<<(unsigned)(n / 4 / 256), 256, 0, s>>>(x, h, l);
}

static void launch_gemm1(const __nv_bfloat16* Ah, const __nv_bfloat16* Al,
                         const __nv_bfloat16* Wh, const __nv_bfloat16* Wl,
                         const float* bias, const float* res, float* C,
                         __nv_bfloat16* Ch, __nv_bfloat16* Cl,
                         int K, int N, int act) {
    GParams p{};
    p.Ah = Ah; p.Al = Al;
    p.Wh[0] = Wh; p.Wl[0] = Wl; p.bias[0] = bias; p.res[0] = res; p.C[0] = C;
    p.Ch[0] = Ch; p.Cl[0] = Cl;
    p.K = K; p.N = N; p.act = act;
    dim3 grid(N / BNT, MM / BMT, 1);
    gemm_bf16_kernel<<<grid, 256, GSMEM_TOTAL>>>(p);
}

static void launch_gemm_big(const __nv_bfloat16* Ah, const __nv_bfloat16* Al,
                            const __nv_bfloat16* Wh, const __nv_bfloat16* Wl,
                            const float* bias, const float* res, float* C,
                            __nv_bfloat16* Ch, __nv_bfloat16* Cl,
                            int K, int N, int act) {
    GParams p{};
    p.Ah = Ah; p.Al = Al;
    p.Wh[0] = Wh; p.Wl[0] = Wl; p.bias[0] = bias; p.res[0] = res; p.C[0] = C;
    p.Ch[0] = Ch; p.Cl[0] = Cl;
    p.K = K; p.N = N; p.act = act;
    dim3 grid(MM / BMT, N / 256, 1);   // x = m (fast), y = n (slow)
    gemm_big_kernel<<<grid, 256, BSMEM_TOTAL>>>(p);
}

extern "C" void kernel_launch(void* const* d_in, const int* in_sizes, int n_in,
                              void* d_out, int out_size) {
    const int*   x     = (const int*)d_in[0];
    const float* emb   = (const float*)d_in[1];
    const float* ln1_w = (const float*)d_in[2];
    const float* ln1_b = (const float*)d_in[3];
    const float* wq_w  = (const float*)d_in[4];
    const float* wq_b  = (const float*)d_in[5];
    const float* wk_w  = (const float*)d_in[6];
    const float* wk_b  = (const float*)d_in[7];
    const float* wv_w  = (const float*)d_in[8];
    const float* wv_b  = (const float*)d_in[9];
    const float* wo_w  = (const float*)d_in[10];
    const float* wo_b  = (const float*)d_in[11];
    const float* ln2_w = (const float*)d_in[12];
    const float* ln2_b = (const float*)d_in[13];
    const float* w1_w  = (const float*)d_in[14];
    const float* w1_b  = (const float*)d_in[15];
    const float* w2_w  = (const float*)d_in[16];
    const float* w2_b  = (const float*)d_in[17];
    const float* lnf_w = (const float*)d_in[18];
    const float* lnf_b = (const float*)d_in[19];
    float* out = (float*)d_out;

    cudaFuncSetAttribute(gemm_bf16_kernel, cudaFuncAttributeMaxDynamicSharedMemorySize,
                         GSMEM_TOTAL);
    cudaFuncSetAttribute(gemm_big_kernel, cudaFuncAttributeMaxDynamicSharedMemorySize,
                         BSMEM_TOTAL);
    cudaFuncSetAttribute(attn_kernel, cudaFuncAttributeMaxDynamicSharedMemorySize,
                         ATT_SMEM);

    float *h;
    __nv_bfloat16 *qh, *ql, *kh, *kl, *vh, *vl;
    __nv_bfloat16 *ah, *al, *bh, *bl, *wh, *wl, *eh, *el;
    cudaGetSymbolAddress((void**)&h,  g_h);
    cudaGetSymbolAddress((void**)&qh, g_qh);
    cudaGetSymbolAddress((void**)&ql, g_ql);
    cudaGetSymbolAddress((void**)&kh, g_kh);
    cudaGetSymbolAddress((void**)&kl, g_kl);
    cudaGetSymbolAddress((void**)&vh, g_vh);
    cudaGetSymbolAddress((void**)&vl, g_vl);
    cudaGetSymbolAddress((void**)&ah, g_ah);
    cudaGetSymbolAddress((void**)&al, g_al);
    cudaGetSymbolAddress((void**)&bh, g_bh);
    cudaGetSymbolAddress((void**)&bl, g_bl);
    cudaGetSymbolAddress((void**)&wh, g_wh);
    cudaGetSymbolAddress((void**)&wl, g_wl);
    cudaGetSymbolAddress((void**)&eh, g_eh);
    cudaGetSymbolAddress((void**)&el, g_el);

    // ---- fork: side stream converts wo/w1/w2/emb while main runs qkv path ----
    cudaEventRecord(g_ss.ev0, 0);
    cudaStreamWaitEvent(g_ss.s2, g_ss.ev0, 0);
    launch_split_s(wo_w, wh + OFF_WO, wl + OFF_WO, (size_t)LL * DD * DD, g_ss.s2);
    launch_split_s(w1_w, wh + OFF_W1, wl + OFF_W1, (size_t)LL * FFD * DD, g_ss.s2);
    launch_split_s(w2_w, wh + OFF_W2, wl + OFF_W2, (size_t)LL * DD * FFD, g_ss.s2);
    cudaEventRecord(g_ss.ev1, g_ss.s2);
    launch_split_s(emb, eh, el, (size_t)VV * DD, g_ss.s2);
    cudaEventRecord(g_ss.ev2, g_ss.s2);

    // ---- main stream: qkv weight splits (needed first) ----
    launch_split_s(wq_w, wh + OFF_WQ, wl + OFF_WQ, (size_t)LL * DD * DD, 0);
    launch_split_s(wk_w, wh + OFF_WK, wl + OFF_WK, (size_t)LL * DD * DD, 0);
    launch_split_s(wv_w, wh + OFF_WV, wl + OFF_WV, (size_t)LL * DD * DD, 0);

    embed_kernel<<<(MM * DD) / 256, 256>>>(x, emb, h);

    for (int l = 0; l < LL; l++) {
        size_t wdd = (size_t)l * DD * DD;
        size_t wfd = (size_t)l * FFD * DD;
        ln_kernel<<<MM, 256>>>(h, ln1_w + (size_t)l * DD, ln1_b + (size_t)l * DD, ah, al);

        {   // batched QKV gemm (3-stage BN=128) -> bf16 hi/lo outputs
            GParams p{};
            p.Ah = ah; p.Al = al;
            p.Wh[0] = wh + OFF_WQ + wdd; p.Wl[0] = wl + OFF_WQ + wdd;
            p.Wh[1] = wh + OFF_WK + wdd; p.Wl[1] = wl + OFF_WK + wdd;
            p.Wh[2] = wh + OFF_WV + wdd; p.Wl[2] = wl + OFF_WV + wdd;
            p.bias[0] = wq_b + (size_t)l * DD;
            p.bias[1] = wk_b + (size_t)l * DD;
            p.bias[2] = wv_b + (size_t)l * DD;
            p.res[0] = p.res[1] = p.res[2] = nullptr;
            p.C[0] = p.C[1] = p.C[2] = nullptr;
            p.Ch[0] = qh; p.Cl[0] = ql;
            p.Ch[1] = kh; p.Cl[1] = kl;
            p.Ch[2] = vh; p.Cl[2] = vl;
            p.K = DD; p.N = DD; p.act = 0;
            dim3 grid(DD / BNT, MM / BMT, 3);
            gemm_bf16_kernel<<<grid, 256, GSMEM_TOTAL>>>(p);
        }

        attn_kernel<<<dim3(SS / 64, BB * HH), 128, ATT_SMEM>>>(qh, ql, kh, kl, vh, vl, ah, al);

        if (l == 0) cudaStreamWaitEvent(0, g_ss.ev1, 0);   // join: wo/w1/w2 splits done

        launch_gemm1(ah, al, wh + OFF_WO + wdd, wl + OFF_WO + wdd,
                     wo_b + (size_t)l * DD, h, h, nullptr, nullptr, DD, DD, 0);

        ln_kernel<<<MM, 256>>>(h, ln2_w + (size_t)l * DD, ln2_b + (size_t)l * DD, ah, al);

        launch_gemm_big(ah, al, wh + OFF_W1 + wfd, wl + OFF_W1 + wfd,
                        w1_b + (size_t)l * FFD, nullptr, nullptr, bh, bl, DD, FFD, 1);

        launch_gemm1(bh, bl, wh + OFF_W2 + wfd, wl + OFF_W2 + wfd,
                     w2_b + (size_t)l * DD, h, h, nullptr, nullptr, FFD, DD, 0);
    }

    ln_kernel<<<MM, 256>>>(h, lnf_w, lnf_b, ah, al);

    cudaStreamWaitEvent(0, g_ss.ev2, 0);   // join: embedding split done

    launch_gemm_big(ah, al, eh, el, nullptr, nullptr, out, nullptr, nullptr, DD, VV, 0);
}

// round 13
// speedup vs baseline: 1.0142x; 1.0142x over previous
#include <cuda_runtime.h>
#include <cuda_bf16.h>
#include <math.h>
#include <stdint.h>

#define VV 32000
#define DD 1024
#define LL 6
#define HH 16
#define FFD 4096
#define SS 1024
#define BB 2
#define DK 64
#define MM (BB*SS)   // 2048 rows

// ---------------- gemm tile config (BN=128, 3-stage) ----------------
#define BMT 128
#define BNT 128
#define KC 64
#define AT_BYTES (BMT*128)
#define WT_BYTES (BNT*128)
#define STAGE_BYTES (2*AT_BYTES + 2*WT_BYTES)   // 65536
#define GSMEM_TOTAL (3*STAGE_BYTES)             // 196608

// ---------------- BIG gemm config (BN=256, 2-stage) ----------------
#define BWT_BYTES (256*128)
#define BSTAGE (2*AT_BYTES + 2*BWT_BYTES)       // 98304
#define BSMEM_TOTAL (2*BSTAGE)                  // 196608

// ---------------- attention smem layout ----------------
#define AQ_H 0
#define AQ_L 8192
#define AK_H 16384
#define AK_L 24576
#define AV_H 32768
#define AV_L 40960
#define ATT_SMEM 49152

// ---------------- whole-model weight split offsets (elements) ----------------
#define OFF_WQ ((size_t)0)
#define OFF_WK ((size_t)6*DD*DD)
#define OFF_WV ((size_t)12*DD*DD)
#define OFF_WO ((size_t)18*DD*DD)
#define OFF_W1 ((size_t)24*DD*DD)
#define OFF_W2 ((size_t)24*DD*DD + (size_t)6*FFD*DD)
#define WTOT   ((size_t)24*DD*DD + (size_t)12*FFD*DD)

// ---------------- scratch ----------------
__device__ float g_h[MM*DD];
__device__ __nv_bfloat16 g_qh[MM*DD];
__device__ __nv_bfloat16 g_ql[MM*DD];
__device__ __nv_bfloat16 g_kh[MM*DD];
__device__ __nv_bfloat16 g_kl[MM*DD];
__device__ __nv_bfloat16 g_vh[MM*DD];
__device__ __nv_bfloat16 g_vl[MM*DD];
__device__ __nv_bfloat16 g_ah[MM*DD];
__device__ __nv_bfloat16 g_al[MM*DD];
__device__ __nv_bfloat16 g_bh[MM*FFD];
__device__ __nv_bfloat16 g_bl[MM*FFD];
__device__ __nv_bfloat16 g_wh[WTOT];
__device__ __nv_bfloat16 g_wl[WTOT];
__device__ __nv_bfloat16 g_eh[VV*DD];
__device__ __nv_bfloat16 g_el[VV*DD];

// ---------------- side stream + events (created once, before any capture) ----------------
struct SideStream {
    cudaStream_t s2;
    cudaEvent_t ev0, evq, ev1, ev2;
    SideStream() {
        cudaStreamCreate(&s2);
        cudaEventCreateWithFlags(&ev0, cudaEventDisableTiming);
        cudaEventCreateWithFlags(&evq, cudaEventDisableTiming);
        cudaEventCreateWithFlags(&ev1, cudaEventDisableTiming);
        cudaEventCreateWithFlags(&ev2, cudaEventDisableTiming);
    }
};
static SideStream g_ss;

// ---------------- helpers ----------------
__device__ __forceinline__ uint32_t smem_u32(const void* p) {
    uint32_t a;
    asm("{ .reg .u64 t; cvta.to.shared.u64 t, %1; cvt.u32.u64 %0, t; }" : "=r"(a) : "l"(p));
    return a;
}
__device__ __forceinline__ float gelu_f(float x) {
    return 0.5f * x * (1.0f + erff(x * 0.70710678118654752f));
}
__device__ __forceinline__ void cp16(uint32_t dst, const void* src) {
    asm volatile("cp.async.cg.shared.global [%0], [%1], 16;" :: "r"(dst), "l"(src));
}
__device__ __forceinline__ void ldmatrix4(uint32_t* r, uint32_t addr) {
    asm volatile("ldmatrix.sync.aligned.m8n8.x4.shared.b16 {%0,%1,%2,%3}, [%4];"
                 : "=r"(r[0]), "=r"(r[1]), "=r"(r[2]), "=r"(r[3]) : "r"(addr));
}
__device__ __forceinline__ void ldmatrix4t(uint32_t* r, uint32_t addr) {
    asm volatile("ldmatrix.sync.aligned.m8n8.x4.trans.shared.b16 {%0,%1,%2,%3}, [%4];"
                 : "=r"(r[0]), "=r"(r[1]), "=r"(r[2]), "=r"(r[3]) : "r"(addr));
}
__device__ __forceinline__ void mma16816(float* c, const uint32_t* a, uint32_t b0, uint32_t b1) {
    asm volatile("mma.sync.aligned.m16n8k16.row.col.f32.bf16.bf16.f32 "
                 "{%0,%1,%2,%3}, {%4,%5,%6,%7}, {%8,%9}, {%0,%1,%2,%3};"
                 : "+f"(c[0]), "+f"(c[1]), "+f"(c[2]), "+f"(c[3])
                 : "r"(a[0]), "r"(a[1]), "r"(a[2]), "r"(a[3]), "r"(b0), "r"(b1));
}
__device__ __forceinline__ __nv_bfloat162 split_hi2(float a, float b) {
    __nv_bfloat162 r; r.x = __float2bfloat16(a); r.y = __float2bfloat16(b); return r;
}
__device__ __forceinline__ __nv_bfloat162 split_lo2(float a, float b, __nv_bfloat162 h) {
    __nv_bfloat162 r;
    r.x = __float2bfloat16(a - __bfloat162float(h.x));
    r.y = __float2bfloat16(b - __bfloat162float(h.y));
    return r;
}
__device__ __forceinline__ uint32_t swzoff(int row, int cu) {
    return (uint32_t)(row * 128 + ((cu * 16) ^ ((row & 7) * 16)));
}

// ---------------- fp32 -> (bf16 hi, bf16 lo) split, 4 elems/thread ----------------
__global__ void split_kernel(const float* __restrict__ x,
                             __nv_bfloat16* __restrict__ h,
                             __nv_bfloat16* __restrict__ l) {
    int i = blockIdx.x * blockDim.x + threadIdx.x;
    float4 v = ((const float4*)x)[i];
    __nv_bfloat162 h0 = split_hi2(v.x, v.y);
    __nv_bfloat162 h1 = split_hi2(v.z, v.w);
    __nv_bfloat162 l0 = split_lo2(v.x, v.y, h0);
    __nv_bfloat162 l1 = split_lo2(v.z, v.w, h1);
    ((__nv_bfloat162*)h)[2*i]   = h0;
    ((__nv_bfloat162*)h)[2*i+1] = h1;
    ((__nv_bfloat162*)l)[2*i]   = l0;
    ((__nv_bfloat162*)l)[2*i+1] = l1;
}

// ---------------- shared GEMM param struct ----------------
struct GParams {
    const __nv_bfloat16 *Ah, *Al;
    const __nv_bfloat16 *Wh[3], *Wl[3];
    const float *bias[3];
    const float *res[3];
    float *C[3];
    __nv_bfloat16 *Ch[3], *Cl[3];
    int K, N, act;
};

__device__ __forceinline__ void ldA(uint32_t* r, uint32_t base, int r0, int kbyte, int lane) {
    int row = r0 + (lane & 15);
    int x = ((lane >> 4) * 16 + kbyte) ^ ((row & 7) * 16);
    ldmatrix4(r, base + row * 128 + x);
}
__device__ __forceinline__ void ldB(uint32_t* r, uint32_t base, int nb, int kbyte, int lane) {
    int nrow = nb + (lane & 7) + ((lane >> 4) << 3);
    int x = (((lane >> 3) & 1) * 16 + kbyte) ^ ((nrow & 7) * 16);
    ldmatrix4(r, base + nrow * 128 + x);
}
__device__ __forceinline__ void ldBt(uint32_t* r, uint32_t base, int nb, int kr0, int lane) {
    int row = kr0 + (lane & 7) + (((lane >> 3) & 1) << 3);
    int colb = nb * 2 + ((lane >> 4) << 4);
    int x = colb ^ ((row & 7) * 16);
    ldmatrix4t(r, base + row * 128 + x);
}

__device__ __forceinline__ void epi_frag(int act, const float* bias, const float* res,
        float* C, __nv_bfloat16* Ch, __nv_bfloat16* Cl,
        float a0, float a1, float a2, float a3,
        int row0, int row1, int col, int N) {
    float v00 = a0, v01 = a1, v10 = a2, v11 = a3;
    if (bias) {
        float2 b2 = *(const float2*)(bias + col);
        v00 += b2.x; v01 += b2.y; v10 += b2.x; v11 += b2.y;
    }
    if (res) {
        float2 r0 = *(const float2*)(res + (size_t)row0 * N + col);
        float2 r1 = *(const float2*)(res + (size_t)row1 * N + col);
        v00 += r0.x; v01 += r0.y; v10 += r1.x; v11 += r1.y;
    }
    if (act) {
        v00 = gelu_f(v00); v01 = gelu_f(v01);
        v10 = gelu_f(v10); v11 = gelu_f(v11);
    }
    if (Ch) {
        __nv_bfloat162 H0 = split_hi2(v00, v01);
        __nv_bfloat162 H1 = split_hi2(v10, v11);
        __nv_bfloat162 L0 = split_lo2(v00, v01, H0);
        __nv_bfloat162 L1 = split_lo2(v10, v11, H1);
        *(__nv_bfloat162*)(Ch + (size_t)row0 * N + col) = H0;
        *(__nv_bfloat162*)(Cl + (size_t)row0 * N + col) = L0;
        *(__nv_bfloat162*)(Ch + (size_t)row1 * N + col) = H1;
        *(__nv_bfloat162*)(Cl + (size_t)row1 * N + col) = L1;
    } else {
        *(float2*)(C + (size_t)row0 * N + col) = make_float2(v00, v01);
        *(float2*)(C + (size_t)row1 * N + col) = make_float2(v10, v11);
    }
}

// ---------------- 3-stage GEMM (BN=128) ----------------
__device__ __forceinline__ void stage_loads(uint32_t sstage,
        const __nv_bfloat16* Ah, const __nv_bfloat16* Al,
        const __nv_bfloat16* Wh, const __nv_bfloat16* Wl,
        int m0, int n0, int k0, int K, int tid) {
    #pragma unroll
    for (int t = 0; t < 4; t++) {
        int u = tid + (t << 8);
        int row = u >> 3, cu = u & 7;
        cp16(sstage + swzoff(row, cu), Ah + (size_t)(m0 + row) * K + k0 + cu * 8);
    }
    #pragma unroll
    for (int t = 0; t < 4; t++) {
        int u = tid + (t << 8);
        int row = u >> 3, cu = u & 7;
        cp16(sstage + AT_BYTES + swzoff(row, cu), Al + (size_t)(m0 + row) * K + k0 + cu * 8);
    }
    #pragma unroll
    for (int t = 0; t < 4; t++) {
        int u = tid + (t << 8);
        int row = u >> 3, cu = u & 7;
        cp16(sstage + 2*AT_BYTES + swzoff(row, cu), Wh + (size_t)(n0 + row) * K + k0 + cu * 8);
    }
    #pragma unroll
    for (int t = 0; t < 4; t++) {
        int u = tid + (t << 8);
        int row = u >> 3, cu = u & 7;
        cp16(sstage + 2*AT_BYTES + WT_BYTES + swzoff(row, cu), Wl + (size_t)(n0 + row) * K + k0 + cu * 8);
    }
    asm volatile("cp.async.commit_group;" ::: "memory");
}

__global__ void __launch_bounds__(256, 1) gemm_bf16_kernel(GParams p) {
    extern __shared__ char smem[];
    const int tid = threadIdx.x;
    const int wid = tid >> 5, lane = tid & 31;
    const int z = blockIdx.z;
    const int m0 = blockIdx.y * BMT, n0 = blockIdx.x * BNT;
    const int K = p.K, N = p.N;
    const __nv_bfloat16* Wh = p.Wh[z];
    const __nv_bfloat16* Wl = p.Wl[z];
    const float* bias = p.bias[z];
    const float* res = p.res[z];
    float* C = p.C[z];
    __nv_bfloat16* Ch = p.Ch[z];
    __nv_bfloat16* Cl = p.Cl[z];
    const uint32_t sb = smem_u32(smem);

    const int wm = (wid >> 1) * 32;
    const int wn = (wid & 1) * 64;

    float acc[2][8][4];
    #pragma unroll
    for (int i = 0; i < 2; i++)
        #pragma unroll
        for (int j = 0; j < 8; j++)
            #pragma unroll
            for (int q = 0; q < 4; q++) acc[i][j][q] = 0.0f;

    const int nch = K / KC;
    stage_loads(sb,                 p.Ah, p.Al, Wh, Wl, m0, n0, 0,    K, tid);
    stage_loads(sb +   STAGE_BYTES, p.Ah, p.Al, Wh, Wl, m0, n0, KC,   K, tid);
    stage_loads(sb + 2*STAGE_BYTES, p.Ah, p.Al, Wh, Wl, m0, n0, 2*KC, K, tid);

    for (int i = 0; i < nch; i++) {
        asm volatile("cp.async.wait_group 2;" ::: "memory");
        __syncthreads();
        uint32_t st = sb + (uint32_t)(i % 3) * STAGE_BYTES;
        uint32_t aH = st, aL = st + AT_BYTES;
        uint32_t wH = st + 2*AT_BYTES, wL = st + 2*AT_BYTES + WT_BYTES;

        #pragma unroll
        for (int ks = 0; ks < 4; ks++) {
            const int kbyte = ks * 32;
            uint32_t ah0[4], ah1[4], al0[4], al1[4];
            ldA(ah0, aH, wm,      kbyte, lane);
            ldA(ah1, aH, wm + 16, kbyte, lane);
            ldA(al0, aL, wm,      kbyte, lane);
            ldA(al1, aL, wm + 16, kbyte, lane);
            uint32_t bh[4][4], bl[4][4];
            #pragma unroll
            for (int g = 0; g < 4; g++) {
                ldB(bh[g], wH, wn + g * 16, kbyte, lane);
                ldB(bl[g], wL, wn + g * 16, kbyte, lane);
            }
            #pragma unroll
            for (int g = 0; g < 4; g++) {
                #pragma unroll
                for (int s = 0; s < 2; s++) {
                    int nj = g * 2 + s;
                    uint32_t h0 = bh[g][s*2], h1 = bh[g][s*2+1];
                    uint32_t l0 = bl[g][s*2], l1 = bl[g][s*2+1];
                    mma16816(acc[0][nj], ah0, h0, h1);
                    mma16816(acc[1][nj], ah1, h0, h1);
                    mma16816(acc[0][nj], al0, h0, h1);
                    mma16816(acc[1][nj], al1, h0, h1);
                    mma16816(acc[0][nj], ah0, l0, l1);
                    mma16816(acc[1][nj], ah1, l0, l1);
                }
            }
        }
        __syncthreads();
        if (i + 3 < nch)
            stage_loads(st, p.Ah, p.Al, Wh, Wl, m0, n0, (i + 3) * KC, K, tid);
    }

    const int lrow = lane >> 2;
    const int lcol = (lane & 3) * 2;
    #pragma unroll
    for (int mi = 0; mi < 2; mi++) {
        int row0 = m0 + wm + mi * 16 + lrow;
        int row1 = row0 + 8;
        #pragma unroll
        for (int nj = 0; nj < 8; nj++) {
            int col = n0 + wn + nj * 8 + lcol;
            epi_frag(p.act, bias, res, C, Ch, Cl, acc[mi][nj][0], acc[mi][nj][1],
                     acc[mi][nj][2], acc[mi][nj][3], row0, row1, col, N);
        }
    }
}

// ---------------- BIG GEMM: 128x256 CTA, 64x64 warp tiles, 2-stage (n-fast grid) -------------
__device__ __forceinline__ void stage_loads_big(uint32_t sstage,
        const __nv_bfloat16* Ah, const __nv_bfloat16* Al,
        const __nv_bfloat16* Wh, const __nv_bfloat16* Wl,
        int m0, int n0, int k0, int K, int tid) {
    #pragma unroll
    for (int t = 0; t < 4; t++) {
        int u = tid + (t << 8);
        int row = u >> 3, cu = u & 7;
        cp16(sstage + swzoff(row, cu), Ah + (size_t)(m0 + row) * K + k0 + cu * 8);
    }
    #pragma unroll
    for (int t = 0; t < 4; t++) {
        int u = tid + (t << 8);
        int row = u >> 3, cu = u & 7;
        cp16(sstage + AT_BYTES + swzoff(row, cu), Al + (size_t)(m0 + row) * K + k0 + cu * 8);
    }
    #pragma unroll
    for (int t = 0; t < 8; t++) {
        int u = tid + (t << 8);
        int row = u >> 3, cu = u & 7;
        cp16(sstage + 2*AT_BYTES + swzoff(row, cu), Wh + (size_t)(n0 + row) * K + k0 + cu * 8);
    }
    #pragma unroll
    for (int t = 0; t < 8; t++) {
        int u = tid + (t << 8);
        int row = u >> 3, cu = u & 7;
        cp16(sstage + 2*AT_BYTES + BWT_BYTES + swzoff(row, cu), Wl + (size_t)(n0 + row) * K + k0 + cu * 8);
    }
    asm volatile("cp.async.commit_group;" ::: "memory");
}

__global__ void __launch_bounds__(256, 1) gemm_big_kernel(GParams p) {
    extern __shared__ char smem[];
    const int tid = threadIdx.x;
    const int wid = tid >> 5, lane = tid & 31;
    const int m0 = blockIdx.y * BMT, n0 = blockIdx.x * 256;
    const int K = p.K, N = p.N;
    const __nv_bfloat16* Wh = p.Wh[0];
    const __nv_bfloat16* Wl = p.Wl[0];
    const float* bias = p.bias[0];
    const float* res = p.res[0];
    float* C = p.C[0];
    __nv_bfloat16* Ch = p.Ch[0];
    __nv_bfloat16* Cl = p.Cl[0];
    const uint32_t sb = smem_u32(smem);

    const int wm = (wid >> 2) * 64;
    const int wn = (wid & 3) * 64;

    float acc[4][8][4];
    #pragma unroll
    for (int m = 0; m < 4; m++)
        #pragma unroll
        for (int j = 0; j < 8; j++)
            #pragma unroll
            for (int q = 0; q < 4; q++) acc[m][j][q] = 0.0f;

    const int nch = K / KC;
    stage_loads_big(sb,          p.Ah, p.Al, Wh, Wl, m0, n0, 0,  K, tid);
    stage_loads_big(sb + BSTAGE, p.Ah, p.Al, Wh, Wl, m0, n0, KC, K, tid);

    for (int i = 0; i < nch; i++) {
        asm volatile("cp.async.wait_group 1;" ::: "memory");
        __syncthreads();
        const uint32_t st = sb + (uint32_t)(i & 1) * BSTAGE;
        const uint32_t aH = st, aL = st + AT_BYTES;
        const uint32_t wH = st + 2*AT_BYTES, wL = st + 2*AT_BYTES + BWT_BYTES;

        #pragma unroll
        for (int ks = 0; ks < 4; ks++) {
            const int kbyte = ks * 32;
            uint32_t ah[4][4], al[4][4];
            #pragma unroll
            for (int m = 0; m < 4; m++) {
                ldA(ah[m], aH, wm + m * 16, kbyte, lane);
                ldA(al[m], aL, wm + m * 16, kbyte, lane);
            }
            #pragma unroll
            for (int g = 0; g < 4; g++) {
                uint32_t bh4[4], bl4[4];
                ldB(bh4, wH, wn + g * 16, kbyte, lane);
                ldB(bl4, wL, wn + g * 16, kbyte, lane);
                #pragma unroll
                for (int s = 0; s < 2; s++) {
                    int nj = g * 2 + s;
                    uint32_t h0 = bh4[s*2], h1 = bh4[s*2+1];
                    uint32_t l0 = bl4[s*2], l1 = bl4[s*2+1];
                    #pragma unroll
                    for (int m = 0; m < 4; m++) {
                        mma16816(acc[m][nj], ah[m], h0, h1);
                        mma16816(acc[m][nj], al[m], h0, h1);
                        mma16816(acc[m][nj], ah[m], l0, l1);
                    }
                }
            }
        }
        __syncthreads();
        if (i + 2 < nch)
            stage_loads_big(st, p.Ah, p.Al, Wh, Wl, m0, n0, (i + 2) * KC, K, tid);
    }

    const int lrow = lane >> 2;
    const int lcol = (lane & 3) * 2;
    #pragma unroll
    for (int m = 0; m < 4; m++) {
        int row0 = m0 + wm + m * 16 + lrow;
        int row1 = row0 + 8;
        #pragma unroll
        for (int nj = 0; nj < 8; nj++) {
            int col = n0 + wn + nj * 8 + lcol;
            epi_frag(p.act, bias, res, C, Ch, Cl, acc[m][nj][0], acc[m][nj][1],
                     acc[m][nj][2], acc[m][nj][3], row0, row1, col, N);
        }
    }
}

// ---------------- embedding + positional encoding ----------------
__global__ void embed_kernel(const int* __restrict__ x, const float* __restrict__ emb,
                             float* __restrict__ h) {
    int idx = blockIdx.x * blockDim.x + threadIdx.x;
    int d  = idx & (DD - 1);
    int bs = idx >> 10;
    int s  = bs & (SS - 1);
    int tok = x[bs];
    int i2 = d & ~1;
    float div = expf(-(float)i2 * (logf(10000.0f) / (float)DD));
    float ang = (float)s * div;
    float pe = (d & 1) ? cosf(ang) : sinf(ang);
    h[idx] = emb[(size_t)tok * DD + d] * 32.0f + pe;
}

// ---------------- layernorm (writes bf16 hi/lo split) ----------------
__global__ void __launch_bounds__(256) ln_kernel(const float* __restrict__ in,
                                                 const float* __restrict__ w,
                                                 const float* __restrict__ b,
                                                 __nv_bfloat16* __restrict__ oh,
                                                 __nv_bfloat16* __restrict__ ol) {
    int row = blockIdx.x;
    int t = threadIdx.x;
    int lane = t & 31, wid = t >> 5;
    __shared__ float red[8];

    float4 x4 = ((const float4*)(in + (size_t)row * DD))[t];
    float s = x4.x + x4.y + x4.z + x4.w;
    #pragma unroll
    for (int o = 16; o; o >>= 1) s += __shfl_xor_sync(0xffffffffu, s, o);
    if (lane == 0) red[wid] = s;
    __syncthreads();
    float tot = red[0]+red[1]+red[2]+red[3]+red[4]+red[5]+red[6]+red[7];
    float mean = tot * (1.0f / DD);
    __syncthreads();

    float d0 = x4.x - mean, d1 = x4.y - mean, d2 = x4.z - mean, d3 = x4.w - mean;
    float vs = d0*d0 + d1*d1 + d2*d2 + d3*d3;
    #pragma unroll
    for (int o = 16; o; o >>= 1) vs += __shfl_xor_sync(0xffffffffu, vs, o);
    if (lane == 0) red[wid] = vs;
    __syncthreads();
    float var = (red[0]+red[1]+red[2]+red[3]+red[4]+red[5]+red[6]+red[7]) * (1.0f / DD);
    float inv = rsqrtf(var + 1e-5f);

    float4 w4 = ((const float4*)w)[t];
    float4 b4 = ((const float4*)b)[t];
    float o0 = d0 * inv * w4.x + b4.x;
    float o1 = d1 * inv * w4.y + b4.y;
    float o2 = d2 * inv * w4.z + b4.z;
    float o3 = d3 * inv * w4.w + b4.w;
    __nv_bfloat162 H0 = split_hi2(o0, o1), H1 = split_hi2(o2, o3);
    __nv_bfloat162 L0 = split_lo2(o0, o1, H0), L1 = split_lo2(o2, o3, H1);
    ((__nv_bfloat162*)(oh + (size_t)row * DD))[2*t]   = H0;
    ((__nv_bfloat162*)(oh + (size_t)row * DD))[2*t+1] = H1;
    ((__nv_bfloat162*)(ol + (size_t)row * DD))[2*t]   = L0;
    ((__nv_bfloat162*)(ol + (size_t)row * DD))[2*t+1] = L1;
}

// ---------------- tensor-core flash attention (R8 proven) ----------------
__device__ __forceinline__ void att_stage(uint32_t dst, const __nv_bfloat16* src,
                                          size_t gbase, int tid) {
    #pragma unroll
    for (int t = 0; t < 4; t++) {
        int u = tid + t * 128;
        int row = u >> 3, cu = u & 7;
        cp16(dst + swzoff(row, cu), src + gbase + (size_t)row * DD + cu * 8);
    }
}

__global__ void __launch_bounds__(128) attn_kernel(
        const __nv_bfloat16* __restrict__ qh, const __nv_bfloat16* __restrict__ ql,
        const __nv_bfloat16* __restrict__ kh, const __nv_bfloat16* __restrict__ kl,
        const __nv_bfloat16* __restrict__ vh, const __nv_bfloat16* __restrict__ vl,
        __nv_bfloat16* __restrict__ ch, __nv_bfloat16* __restrict__ cl) {
    extern __shared__ char asmem[];
    const uint32_t sb = smem_u32(asmem);
    const int qt = blockIdx.x;
    const int bh = blockIdx.y;
    const int hh = bh & (HH - 1);
    const int bb = bh >> 4;
    const int q0 = qt * 64;

    const int tid = threadIdx.x;
    const int wid = tid >> 5, lane = tid & 31;
    const int wq = wid * 16;

    const size_t qbase = (size_t)(bb * SS + q0) * DD + hh * DK;
    att_stage(sb + AQ_H, qh, qbase, tid);
    att_stage(sb + AQ_L, ql, qbase, tid);
    asm volatile("cp.async.commit_group;" ::: "memory");

    float m0 = -1e30f, m1 = -1e30f, l0s = 0.0f, l1s = 0.0f;
    float ctx[8][4];
    #pragma unroll
    for (int j = 0; j < 8; j++)
        #pragma unroll
        for (int e = 0; e < 4; e++) ctx[j][e] = 0.0f;

    const int r = lane >> 2;
    const int cb = (lane & 3) * 2;

    const int ntiles = qt + 1;
    for (int t = 0; t < ntiles; t++) {
        __syncthreads();
        const size_t kbase = (size_t)(bb * SS + t * 64) * DD + hh * DK;
        att_stage(sb + AK_H, kh, kbase, tid);
        att_stage(sb + AK_L, kl, kbase, tid);
        att_stage(sb + AV_H, vh, kbase, tid);
        att_stage(sb + AV_L, vl, kbase, tid);
        asm volatile("cp.async.commit_group;" ::: "memory");
        asm volatile("cp.async.wait_group 0;" ::: "memory");
        __syncthreads();

        float sc[8][4];
        #pragma unroll
        for (int j = 0; j < 8; j++)
            #pragma unroll
            for (int e = 0; e < 4; e++) sc[j][e] = 0.0f;

        #pragma unroll
        for (int ks = 0; ks < 4; ks++) {
            const int kb = ks * 32;
            uint32_t qhf[4], qlf[4];
            ldA(qhf, sb + AQ_H, wq, kb, lane);
            ldA(qlf, sb + AQ_L, wq, kb, lane);
            #pragma unroll
            for (int g = 0; g < 4; g++) {
                uint32_t khf[4], klf[4];
                ldB(khf, sb + AK_H, g * 16, kb, lane);
                ldB(klf, sb + AK_L, g * 16, kb, lane);
                #pragma unroll
                for (int s = 0; s < 2; s++) {
                    int nj = g * 2 + s;
                    mma16816(sc[nj], qhf, khf[s*2], khf[s*2+1]);
                    mma16816(sc[nj], qlf, khf[s*2], khf[s*2+1]);
                    mma16816(sc[nj], qhf, klf[s*2], klf[s*2+1]);
                }
            }
        }
        #pragma unroll
        for (int nj = 0; nj < 8; nj++) {
            sc[nj][0] *= 0.125f; sc[nj][1] *= 0.125f;
            sc[nj][2] *= 0.125f; sc[nj][3] *= 0.125f;
        }

        if (t == qt) {
            #pragma unroll
            for (int nj = 0; nj < 8; nj++) {
                int c0 = nj * 8 + cb;
                if (c0     > wq + r)     sc[nj][0] = -1e30f;
                if (c0 + 1 > wq + r)     sc[nj][1] = -1e30f;
                if (c0     > wq + r + 8) sc[nj][2] = -1e30f;
                if (c0 + 1 > wq + r + 8) sc[nj][3] = -1e30f;
            }
        }

        float tm0 = -1e30f, tm1 = -1e30f;
        #pragma unroll
        for (int nj = 0; nj < 8; nj++) {
            tm0 = fmaxf(tm0, fmaxf(sc[nj][0], sc[nj][1]));
            tm1 = fmaxf(tm1, fmaxf(sc[nj][2], sc[nj][3]));
        }
        tm0 = fmaxf(tm0, __shfl_xor_sync(0xffffffffu, tm0, 1));
        tm0 = fmaxf(tm0, __shfl_xor_sync(0xffffffffu, tm0, 2));
        tm1 = fmaxf(tm1, __shfl_xor_sync(0xffffffffu, tm1, 1));
        tm1 = fmaxf(tm1, __shfl_xor_sync(0xffffffffu, tm1, 2));
        float m0n = fmaxf(m0, tm0), m1n = fmaxf(m1, tm1);
        float a0 = __expf(m0 - m0n), a1 = __expf(m1 - m1n);
        float sum0 = 0.0f, sum1 = 0.0f;
        #pragma unroll
        for (int nj = 0; nj < 8; nj++) {
            sc[nj][0] = __expf(sc[nj][0] - m0n);
            sc[nj][1] = __expf(sc[nj][1] - m0n);
            sc[nj][2] = __expf(sc[nj][2] - m1n);
            sc[nj][3] = __expf(sc[nj][3] - m1n);
            sum0 += sc[nj][0] + sc[nj][1];
            sum1 += sc[nj][2] + sc[nj][3];
        }
        sum0 += __shfl_xor_sync(0xffffffffu, sum0, 1);
        sum0 += __shfl_xor_sync(0xffffffffu, sum0, 2);
        sum1 += __shfl_xor_sync(0xffffffffu, sum1, 1);
        sum1 += __shfl_xor_sync(0xffffffffu, sum1, 2);
        l0s = l0s * a0 + sum0;
        l1s = l1s * a1 + sum1;
        m0 = m0n; m1 = m1n;
        #pragma unroll
        for (int nj = 0; nj < 8; nj++) {
            ctx[nj][0] *= a0; ctx[nj][1] *= a0;
            ctx[nj][2] *= a1; ctx[nj][3] *= a1;
        }

        #pragma unroll
        for (int ks = 0; ks < 4; ks++) {
            uint32_t ph[4], pl[4];
            {
                __nv_bfloat162 t0 = split_hi2(sc[2*ks][0],   sc[2*ks][1]);
                __nv_bfloat162 t1 = split_hi2(sc[2*ks][2],   sc[2*ks][3]);
                __nv_bfloat162 t2 = split_hi2(sc[2*ks+1][0], sc[2*ks+1][1]);
                __nv_bfloat162 t3 = split_hi2(sc[2*ks+1][2], sc[2*ks+1][3]);
                ph[0] = *(uint32_t*)&t0; ph[1] = *(uint32_t*)&t1;
                ph[2] = *(uint32_t*)&t2; ph[3] = *(uint32_t*)&t3;
                __nv_bfloat162 u0 = split_lo2(sc[2*ks][0],   sc[2*ks][1],   t0);
                __nv_bfloat162 u1 = split_lo2(sc[2*ks][2],   sc[2*ks][3],   t1);
                __nv_bfloat162 u2 = split_lo2(sc[2*ks+1][0], sc[2*ks+1][1], t2);
                __nv_bfloat162 u3 = split_lo2(sc[2*ks+1][2], sc[2*ks+1][3], t3);
                pl[0] = *(uint32_t*)&u0; pl[1] = *(uint32_t*)&u1;
                pl[2] = *(uint32_t*)&u2; pl[3] = *(uint32_t*)&u3;
            }
            const int kr0 = ks * 16;
            #pragma unroll
            for (int g = 0; g < 4; g++) {
                uint32_t vhf[4], vlf[4];
                ldBt(vhf, sb + AV_H, g * 16, kr0, lane);
                ldBt(vlf, sb + AV_L, g * 16, kr0, lane);
                #pragma unroll
                for (int s = 0; s < 2; s++) {
                    int nj = g * 2 + s;
                    mma16816(ctx[nj], ph, vhf[s*2], vhf[s*2+1]);
                    mma16816(ctx[nj], ph, vlf[s*2], vlf[s*2+1]);
                    mma16816(ctx[nj], pl, vhf[s*2], vhf[s*2+1]);
                }
            }
        }
    }

    float i0 = 1.0f / l0s, i1 = 1.0f / l1s;
    size_t row0 = (size_t)(bb * SS + q0 + wq + r) * DD + hh * DK;
    size_t row1 = row0 + (size_t)8 * DD;
    #pragma unroll
    for (int nj = 0; nj < 8; nj++) {
        int d = nj * 8 + cb;
        float x0 = ctx[nj][0] * i0, x1 = ctx[nj][1] * i0;
        __nv_bfloat162 H = split_hi2(x0, x1);
        __nv_bfloat162 L = split_lo2(x0, x1, H);
        *(__nv_bfloat162*)(ch + row0 + d) = H;
        *(__nv_bfloat162*)(cl + row0 + d) = L;
        float y0 = ctx[nj][2] * i1, y1 = ctx[nj][3] * i1;
        __nv_bfloat162 H1 = split_hi2(y0, y1);
        __nv_bfloat162 L1 = split_lo2(y0, y1, H1);
        *(__nv_bfloat162*)(ch + row1 + d) = H1;
        *(__nv_bfloat162*)(cl + row1 + d) = L1;
    }
}

// ---------------- host-side launch helpers ----------------
static void launch_split_s(const float* x, __nv_bfloat16* h, __nv_bfloat16* l,
                           size_t n, cudaStream_t s) {
    split_kernel<<<(unsigned)(n / 4 / 256), 256, 0, s>>>(x, h, l);
}

static void launch_gemm1(const __nv_bfloat16* Ah, const __nv_bfloat16* Al,
                         const __nv_bfloat16* Wh, const __nv_bfloat16* Wl,
                         const float* bias, const float* res, float* C,
                         __nv_bfloat16* Ch, __nv_bfloat16* Cl,
                         int K, int N, int act) {
    GParams p{};
    p.Ah = Ah; p.Al = Al;
    p.Wh[0] = Wh; p.Wl[0] = Wl; p.bias[0] = bias; p.res[0] = res; p.C[0] = C;
    p.Ch[0] = Ch; p.Cl[0] = Cl;
    p.K = K; p.N = N; p.act = act;
    dim3 grid(N / BNT, MM / BMT, 1);
    gemm_bf16_kernel<<<grid, 256, GSMEM_TOTAL>>>(p);
}

static void launch_gemm_big(const __nv_bfloat16* Ah, const __nv_bfloat16* Al,
                            const __nv_bfloat16* Wh, const __nv_bfloat16* Wl,
                            const float* bias, const float* res, float* C,
                            __nv_bfloat16* Ch, __nv_bfloat16* Cl,
                            int K, int N, int act) {
    GParams p{};
    p.Ah = Ah; p.Al = Al;
    p.Wh[0] = Wh; p.Wl[0] = Wl; p.bias[0] = bias; p.res[0] = res; p.C[0] = C;
    p.Ch[0] = Ch; p.Cl[0] = Cl;
    p.K = K; p.N = N; p.act = act;
    dim3 grid(N / 256, MM / BMT, 1);   // n-fast (R11 proven)
    gemm_big_kernel<<<grid, 256, BSMEM_TOTAL>>>(p);
}

extern "C" void kernel_launch(void* const* d_in, const int* in_sizes, int n_in,
                              void* d_out, int out_size) {
    const int*   x     = (const int*)d_in[0];
    const float* emb   = (const float*)d_in[1];
    const float* ln1_w = (const float*)d_in[2];
    const float* ln1_b = (const float*)d_in[3];
    const float* wq_w  = (const float*)d_in[4];
    const float* wq_b  = (const float*)d_in[5];
    const float* wk_w  = (const float*)d_in[6];
    const float* wk_b  = (const float*)d_in[7];
    const float* wv_w  = (const float*)d_in[8];
    const float* wv_b  = (const float*)d_in[9];
    const float* wo_w  = (const float*)d_in[10];
    const float* wo_b  = (const float*)d_in[11];
    const float* ln2_w = (const float*)d_in[12];
    const float* ln2_b = (const float*)d_in[13];
    const float* w1_w  = (const float*)d_in[14];
    const float* w1_b  = (const float*)d_in[15];
    const float* w2_w  = (const float*)d_in[16];
    const float* w2_b  = (const float*)d_in[17];
    const float* lnf_w = (const float*)d_in[18];
    const float* lnf_b = (const float*)d_in[19];
    float* out = (float*)d_out;

    cudaFuncSetAttribute(gemm_bf16_kernel, cudaFuncAttributeMaxDynamicSharedMemorySize,
                         GSMEM_TOTAL);
    cudaFuncSetAttribute(gemm_big_kernel, cudaFuncAttributeMaxDynamicSharedMemorySize,
                         BSMEM_TOTAL);
    cudaFuncSetAttribute(attn_kernel, cudaFuncAttributeMaxDynamicSharedMemorySize,
                         ATT_SMEM);

    float *h;
    __nv_bfloat16 *qh, *ql, *kh, *kl, *vh, *vl;
    __nv_bfloat16 *ah, *al, *bh, *bl, *wh, *wl, *eh, *el;
    cudaGetSymbolAddress((void**)&h,  g_h);
    cudaGetSymbolAddress((void**)&qh, g_qh);
    cudaGetSymbolAddress((void**)&ql, g_ql);
    cudaGetSymbolAddress((void**)&kh, g_kh);
    cudaGetSymbolAddress((void**)&kl, g_kl);
    cudaGetSymbolAddress((void**)&vh, g_vh);
    cudaGetSymbolAddress((void**)&vl, g_vl);
    cudaGetSymbolAddress((void**)&ah, g_ah);
    cudaGetSymbolAddress((void**)&al, g_al);
    cudaGetSymbolAddress((void**)&bh, g_bh);
    cudaGetSymbolAddress((void**)&bl, g_bl);
    cudaGetSymbolAddress((void**)&wh, g_wh);
    cudaGetSymbolAddress((void**)&wl, g_wl);
    cudaGetSymbolAddress((void**)&eh, g_eh);
    cudaGetSymbolAddress((void**)&el, g_el);

    // ---- fork: ALL weight splits on the side stream ----
    cudaEventRecord(g_ss.ev0, 0);
    cudaStreamWaitEvent(g_ss.s2, g_ss.ev0, 0);
    launch_split_s(wq_w, wh + OFF_WQ, wl + OFF_WQ, (size_t)LL * DD * DD, g_ss.s2);
    launch_split_s(wk_w, wh + OFF_WK, wl + OFF_WK, (size_t)LL * DD * DD, g_ss.s2);
    launch_split_s(wv_w, wh + OFF_WV, wl + OFF_WV, (size_t)LL * DD * DD, g_ss.s2);
    cudaEventRecord(g_ss.evq, g_ss.s2);
    launch_split_s(wo_w, wh + OFF_WO, wl + OFF_WO, (size_t)LL * DD * DD, g_ss.s2);
    launch_split_s(w1_w, wh + OFF_W1, wl + OFF_W1, (size_t)LL * FFD * DD, g_ss.s2);
    launch_split_s(w2_w, wh + OFF_W2, wl + OFF_W2, (size_t)LL * DD * FFD, g_ss.s2);
    cudaEventRecord(g_ss.ev1, g_ss.s2);
    launch_split_s(emb, eh, el, (size_t)VV * DD, g_ss.s2);
    cudaEventRecord(g_ss.ev2, g_ss.s2);

    // ---- main stream: embedding + layer loop ----
    embed_kernel<<<(MM * DD) / 256, 256>>>(x, emb, h);

    for (int l = 0; l < LL; l++) {
        size_t wdd = (size_t)l * DD * DD;
        size_t wfd = (size_t)l * FFD * DD;
        ln_kernel<<<MM, 256>>>(h, ln1_w + (size_t)l * DD, ln1_b + (size_t)l * DD, ah, al);

        if (l == 0) cudaStreamWaitEvent(0, g_ss.evq, 0);   // join: qkv splits done

        {   // batched QKV gemm (3-stage BN=128) -> bf16 hi/lo outputs
            GParams p{};
            p.Ah = ah; p.Al = al;
            p.Wh[0] = wh + OFF_WQ + wdd; p.Wl[0] = wl + OFF_WQ + wdd;
            p.Wh[1] = wh + OFF_WK + wdd; p.Wl[1] = wl + OFF_WK + wdd;
            p.Wh[2] = wh + OFF_WV + wdd; p.Wl[2] = wl + OFF_WV + wdd;
            p.bias[0] = wq_b + (size_t)l * DD;
            p.bias[1] = wk_b + (size_t)l * DD;
            p.bias[2] = wv_b + (size_t)l * DD;
            p.res[0] = p.res[1] = p.res[2] = nullptr;
            p.C[0] = p.C[1] = p.C[2] = nullptr;
            p.Ch[0] = qh; p.Cl[0] = ql;
            p.Ch[1] = kh; p.Cl[1] = kl;
            p.Ch[2] = vh; p.Cl[2] = vl;
            p.K = DD; p.N = DD; p.act = 0;
            dim3 grid(DD / BNT, MM / BMT, 3);
            gemm_bf16_kernel<<<grid, 256, GSMEM_TOTAL>>>(p);
        }

        attn_kernel<<<dim3(SS / 64, BB * HH), 128, ATT_SMEM>>>(qh, ql, kh, kl, vh, vl, ah, al);

        if (l == 0) cudaStreamWaitEvent(0, g_ss.ev1, 0);   // join: wo/w1/w2 splits done

        launch_gemm1(ah, al, wh + OFF_WO + wdd, wl + OFF_WO + wdd,
                     wo_b + (size_t)l * DD, h, h, nullptr, nullptr, DD, DD, 0);

        ln_kernel<<<MM, 256>>>(h, ln2_w + (size_t)l * DD, ln2_b + (size_t)l * DD, ah, al);

        launch_gemm_big(ah, al, wh + OFF_W1 + wfd, wl + OFF_W1 + wfd,
                        w1_b + (size_t)l * FFD, nullptr, nullptr, bh, bl, DD, FFD, 1);

        launch_gemm1(bh, bl, wh + OFF_W2 + wfd, wl + OFF_W2 + wfd,
                     w2_b + (size_t)l * DD, h, h, nullptr, nullptr, FFD, DD, 0);
    }

    ln_kernel<<<MM, 256>>>(h, lnf_w, lnf_b, ah, al);

    cudaStreamWaitEvent(0, g_ss.ev2, 0);   // join: embedding split done

    launch_gemm_big(ah, al, eh, el, nullptr, nullptr, out, nullptr, nullptr, DD, VV, 0);
}

// round 14
// speedup vs baseline: 1.0185x; 1.0042x over previous
#include <cuda_runtime.h>
#include <cuda_bf16.h>
#include <math.h>
#include <stdint.h>

#define VV 32000
#define DD 1024
#define LL 6
#define HH 16
#define FFD 4096
#define SS 1024
#define BB 2
#define DK 64
#define MM (BB*SS)   // 2048 rows

// ---------------- gemm tile config (BN=128, 3-stage) ----------------
#define BMT 128
#define BNT 128
#define KC 64
#define AT_BYTES (BMT*128)
#define WT_BYTES (BNT*128)
#define STAGE_BYTES (2*AT_BYTES + 2*WT_BYTES)   // 65536
#define GSMEM_TOTAL (3*STAGE_BYTES)             // 196608

// ---------------- BIG gemm config (BN=256, 2-stage) ----------------
#define BWT_BYTES (256*128)
#define BSTAGE (2*AT_BYTES + 2*BWT_BYTES)       // 98304
#define BSMEM_TOTAL (2*BSTAGE)                  // 196608

// ---------------- attention smem: 2 K/V stages of 32KB; Q staged in stage1 then regs ----
#define AST_BYTES 32768
#define AK_H 0
#define AK_L 8192
#define AV_H 16384
#define AV_L 24576
#define ATT_SMEM (2*AST_BYTES)    // 65536

// ---------------- whole-model weight split offsets (elements) ----------------
#define OFF_WQ ((size_t)0)
#define OFF_WK ((size_t)6*DD*DD)
#define OFF_WV ((size_t)12*DD*DD)
#define OFF_WO ((size_t)18*DD*DD)
#define OFF_W1 ((size_t)24*DD*DD)
#define OFF_W2 ((size_t)24*DD*DD + (size_t)6*FFD*DD)
#define WTOT   ((size_t)24*DD*DD + (size_t)12*FFD*DD)

// ---------------- scratch ----------------
__device__ float g_h[MM*DD];
__device__ __nv_bfloat16 g_qh[MM*DD];
__device__ __nv_bfloat16 g_ql[MM*DD];
__device__ __nv_bfloat16 g_kh[MM*DD];
__device__ __nv_bfloat16 g_kl[MM*DD];
__device__ __nv_bfloat16 g_vh[MM*DD];
__device__ __nv_bfloat16 g_vl[MM*DD];
__device__ __nv_bfloat16 g_ah[MM*DD];
__device__ __nv_bfloat16 g_al[MM*DD];
__device__ __nv_bfloat16 g_bh[MM*FFD];
__device__ __nv_bfloat16 g_bl[MM*FFD];
__device__ __nv_bfloat16 g_wh[WTOT];
__device__ __nv_bfloat16 g_wl[WTOT];
__device__ __nv_bfloat16 g_eh[VV*DD];
__device__ __nv_bfloat16 g_el[VV*DD];

// ---------------- side stream + events (created once, before any capture) ----------------
struct SideStream {
    cudaStream_t s2;
    cudaEvent_t ev0, evq, ev1, ev2;
    SideStream() {
        cudaStreamCreate(&s2);
        cudaEventCreateWithFlags(&ev0, cudaEventDisableTiming);
        cudaEventCreateWithFlags(&evq, cudaEventDisableTiming);
        cudaEventCreateWithFlags(&ev1, cudaEventDisableTiming);
        cudaEventCreateWithFlags(&ev2, cudaEventDisableTiming);
    }
};
static SideStream g_ss;

// ---------------- helpers ----------------
__device__ __forceinline__ uint32_t smem_u32(const void* p) {
    uint32_t a;
    asm("{ .reg .u64 t; cvta.to.shared.u64 t, %1; cvt.u32.u64 %0, t; }" : "=r"(a) : "l"(p));
    return a;
}
__device__ __forceinline__ float gelu_f(float x) {
    return 0.5f * x * (1.0f + erff(x * 0.70710678118654752f));
}
__device__ __forceinline__ void cp16(uint32_t dst, const void* src) {
    asm volatile("cp.async.cg.shared.global [%0], [%1], 16;" :: "r"(dst), "l"(src));
}
__device__ __forceinline__ void ldmatrix4(uint32_t* r, uint32_t addr) {
    asm volatile("ldmatrix.sync.aligned.m8n8.x4.shared.b16 {%0,%1,%2,%3}, [%4];"
                 : "=r"(r[0]), "=r"(r[1]), "=r"(r[2]), "=r"(r[3]) : "r"(addr));
}
__device__ __forceinline__ void ldmatrix4t(uint32_t* r, uint32_t addr) {
    asm volatile("ldmatrix.sync.aligned.m8n8.x4.trans.shared.b16 {%0,%1,%2,%3}, [%4];"
                 : "=r"(r[0]), "=r"(r[1]), "=r"(r[2]), "=r"(r[3]) : "r"(addr));
}
__device__ __forceinline__ void mma16816(float* c, const uint32_t* a, uint32_t b0, uint32_t b1) {
    asm volatile("mma.sync.aligned.m16n8k16.row.col.f32.bf16.bf16.f32 "
                 "{%0,%1,%2,%3}, {%4,%5,%6,%7}, {%8,%9}, {%0,%1,%2,%3};"
                 : "+f"(c[0]), "+f"(c[1]), "+f"(c[2]), "+f"(c[3])
                 : "r"(a[0]), "r"(a[1]), "r"(a[2]), "r"(a[3]), "r"(b0), "r"(b1));
}
__device__ __forceinline__ __nv_bfloat162 split_hi2(float a, float b) {
    __nv_bfloat162 r; r.x = __float2bfloat16(a); r.y = __float2bfloat16(b); return r;
}
__device__ __forceinline__ __nv_bfloat162 split_lo2(float a, float b, __nv_bfloat162 h) {
    __nv_bfloat162 r;
    r.x = __float2bfloat16(a - __bfloat162float(h.x));
    r.y = __float2bfloat16(b - __bfloat162float(h.y));
    return r;
}
__device__ __forceinline__ uint32_t swzoff(int row, int cu) {
    return (uint32_t)(row * 128 + ((cu * 16) ^ ((row & 7) * 16)));
}

// ---------------- fp32 -> (bf16 hi, bf16 lo) split, 4 elems/thread ----------------
__global__ void split_kernel(const float* __restrict__ x,
                             __nv_bfloat16* __restrict__ h,
                             __nv_bfloat16* __restrict__ l) {
    int i = blockIdx.x * blockDim.x + threadIdx.x;
    float4 v = ((const float4*)x)[i];
    __nv_bfloat162 h0 = split_hi2(v.x, v.y);
    __nv_bfloat162 h1 = split_hi2(v.z, v.w);
    __nv_bfloat162 l0 = split_lo2(v.x, v.y, h0);
    __nv_bfloat162 l1 = split_lo2(v.z, v.w, h1);
    ((__nv_bfloat162*)h)[2*i]   = h0;
    ((__nv_bfloat162*)h)[2*i+1] = h1;
    ((__nv_bfloat162*)l)[2*i]   = l0;
    ((__nv_bfloat162*)l)[2*i+1] = l1;
}

// ---------------- shared GEMM param struct ----------------
struct GParams {
    const __nv_bfloat16 *Ah, *Al;
    const __nv_bfloat16 *Wh[3], *Wl[3];
    const float *bias[3];
    const float *res[3];
    float *C[3];
    __nv_bfloat16 *Ch[3], *Cl[3];
    int K, N, act;
};

__device__ __forceinline__ void ldA(uint32_t* r, uint32_t base, int r0, int kbyte, int lane) {
    int row = r0 + (lane & 15);
    int x = ((lane >> 4) * 16 + kbyte) ^ ((row & 7) * 16);
    ldmatrix4(r, base + row * 128 + x);
}
__device__ __forceinline__ void ldB(uint32_t* r, uint32_t base, int nb, int kbyte, int lane) {
    int nrow = nb + (lane & 7) + ((lane >> 4) << 3);
    int x = (((lane >> 3) & 1) * 16 + kbyte) ^ ((nrow & 7) * 16);
    ldmatrix4(r, base + nrow * 128 + x);
}
__device__ __forceinline__ void ldBt(uint32_t* r, uint32_t base, int nb, int kr0, int lane) {
    int row = kr0 + (lane & 7) + (((lane >> 3) & 1) << 3);
    int colb = nb * 2 + ((lane >> 4) << 4);
    int x = colb ^ ((row & 7) * 16);
    ldmatrix4t(r, base + row * 128 + x);
}

__device__ __forceinline__ void epi_frag(int act, const float* bias, const float* res,
        float* C, __nv_bfloat16* Ch, __nv_bfloat16* Cl,
        float a0, float a1, float a2, float a3,
        int row0, int row1, int col, int N) {
    float v00 = a0, v01 = a1, v10 = a2, v11 = a3;
    if (bias) {
        float2 b2 = *(const float2*)(bias + col);
        v00 += b2.x; v01 += b2.y; v10 += b2.x; v11 += b2.y;
    }
    if (res) {
        float2 r0 = *(const float2*)(res + (size_t)row0 * N + col);
        float2 r1 = *(const float2*)(res + (size_t)row1 * N + col);
        v00 += r0.x; v01 += r0.y; v10 += r1.x; v11 += r1.y;
    }
    if (act) {
        v00 = gelu_f(v00); v01 = gelu_f(v01);
        v10 = gelu_f(v10); v11 = gelu_f(v11);
    }
    if (Ch) {
        __nv_bfloat162 H0 = split_hi2(v00, v01);
        __nv_bfloat162 H1 = split_hi2(v10, v11);
        __nv_bfloat162 L0 = split_lo2(v00, v01, H0);
        __nv_bfloat162 L1 = split_lo2(v10, v11, H1);
        *(__nv_bfloat162*)(Ch + (size_t)row0 * N + col) = H0;
        *(__nv_bfloat162*)(Cl + (size_t)row0 * N + col) = L0;
        *(__nv_bfloat162*)(Ch + (size_t)row1 * N + col) = H1;
        *(__nv_bfloat162*)(Cl + (size_t)row1 * N + col) = L1;
    } else {
        *(float2*)(C + (size_t)row0 * N + col) = make_float2(v00, v01);
        *(float2*)(C + (size_t)row1 * N + col) = make_float2(v10, v11);
    }
}

// ---------------- 3-stage GEMM (BN=128) ----------------
__device__ __forceinline__ void stage_loads(uint32_t sstage,
        const __nv_bfloat16* Ah, const __nv_bfloat16* Al,
        const __nv_bfloat16* Wh, const __nv_bfloat16* Wl,
        int m0, int n0, int k0, int K, int tid) {
    #pragma unroll
    for (int t = 0; t < 4; t++) {
        int u = tid + (t << 8);
        int row = u >> 3, cu = u & 7;
        cp16(sstage + swzoff(row, cu), Ah + (size_t)(m0 + row) * K + k0 + cu * 8);
    }
    #pragma unroll
    for (int t = 0; t < 4; t++) {
        int u = tid + (t << 8);
        int row = u >> 3, cu = u & 7;
        cp16(sstage + AT_BYTES + swzoff(row, cu), Al + (size_t)(m0 + row) * K + k0 + cu * 8);
    }
    #pragma unroll
    for (int t = 0; t < 4; t++) {
        int u = tid + (t << 8);
        int row = u >> 3, cu = u & 7;
        cp16(sstage + 2*AT_BYTES + swzoff(row, cu), Wh + (size_t)(n0 + row) * K + k0 + cu * 8);
    }
    #pragma unroll
    for (int t = 0; t < 4; t++) {
        int u = tid + (t << 8);
        int row = u >> 3, cu = u & 7;
        cp16(sstage + 2*AT_BYTES + WT_BYTES + swzoff(row, cu), Wl + (size_t)(n0 + row) * K + k0 + cu * 8);
    }
    asm volatile("cp.async.commit_group;" ::: "memory");
}

__global__ void __launch_bounds__(256, 1) gemm_bf16_kernel(GParams p) {
    extern __shared__ char smem[];
    const int tid = threadIdx.x;
    const int wid = tid >> 5, lane = tid & 31;
    const int z = blockIdx.z;
    const int m0 = blockIdx.y * BMT, n0 = blockIdx.x * BNT;
    const int K = p.K, N = p.N;
    const __nv_bfloat16* Wh = p.Wh[z];
    const __nv_bfloat16* Wl = p.Wl[z];
    const float* bias = p.bias[z];
    const float* res = p.res[z];
    float* C = p.C[z];
    __nv_bfloat16* Ch = p.Ch[z];
    __nv_bfloat16* Cl = p.Cl[z];
    const uint32_t sb = smem_u32(smem);

    const int wm = (wid >> 1) * 32;
    const int wn = (wid & 1) * 64;

    float acc[2][8][4];
    #pragma unroll
    for (int i = 0; i < 2; i++)
        #pragma unroll
        for (int j = 0; j < 8; j++)
            #pragma unroll
            for (int q = 0; q < 4; q++) acc[i][j][q] = 0.0f;

    const int nch = K / KC;
    stage_loads(sb,                 p.Ah, p.Al, Wh, Wl, m0, n0, 0,    K, tid);
    stage_loads(sb +   STAGE_BYTES, p.Ah, p.Al, Wh, Wl, m0, n0, KC,   K, tid);
    stage_loads(sb + 2*STAGE_BYTES, p.Ah, p.Al, Wh, Wl, m0, n0, 2*KC, K, tid);

    for (int i = 0; i < nch; i++) {
        asm volatile("cp.async.wait_group 2;" ::: "memory");
        __syncthreads();
        uint32_t st = sb + (uint32_t)(i % 3) * STAGE_BYTES;
        uint32_t aH = st, aL = st + AT_BYTES;
        uint32_t wH = st + 2*AT_BYTES, wL = st + 2*AT_BYTES + WT_BYTES;

        #pragma unroll
        for (int ks = 0; ks < 4; ks++) {
            const int kbyte = ks * 32;
            uint32_t ah0[4], ah1[4], al0[4], al1[4];
            ldA(ah0, aH, wm,      kbyte, lane);
            ldA(ah1, aH, wm + 16, kbyte, lane);
            ldA(al0, aL, wm,      kbyte, lane);
            ldA(al1, aL, wm + 16, kbyte, lane);
            uint32_t bh[4][4], bl[4][4];
            #pragma unroll
            for (int g = 0; g < 4; g++) {
                ldB(bh[g], wH, wn + g * 16, kbyte, lane);
                ldB(bl[g], wL, wn + g * 16, kbyte, lane);
            }
            #pragma unroll
            for (int g = 0; g < 4; g++) {
                #pragma unroll
                for (int s = 0; s < 2; s++) {
                    int nj = g * 2 + s;
                    uint32_t h0 = bh[g][s*2], h1 = bh[g][s*2+1];
                    uint32_t l0 = bl[g][s*2], l1 = bl[g][s*2+1];
                    mma16816(acc[0][nj], ah0, h0, h1);
                    mma16816(acc[1][nj], ah1, h0, h1);
                    mma16816(acc[0][nj], al0, h0, h1);
                    mma16816(acc[1][nj], al1, h0, h1);
                    mma16816(acc[0][nj], ah0, l0, l1);
                    mma16816(acc[1][nj], ah1, l0, l1);
                }
            }
        }
        __syncthreads();
        if (i + 3 < nch)
            stage_loads(st, p.Ah, p.Al, Wh, Wl, m0, n0, (i + 3) * KC, K, tid);
    }

    const int lrow = lane >> 2;
    const int lcol = (lane & 3) * 2;
    #pragma unroll
    for (int mi = 0; mi < 2; mi++) {
        int row0 = m0 + wm + mi * 16 + lrow;
        int row1 = row0 + 8;
        #pragma unroll
        for (int nj = 0; nj < 8; nj++) {
            int col = n0 + wn + nj * 8 + lcol;
            epi_frag(p.act, bias, res, C, Ch, Cl, acc[mi][nj][0], acc[mi][nj][1],
                     acc[mi][nj][2], acc[mi][nj][3], row0, row1, col, N);
        }
    }
}

// ---------------- BIG GEMM: 128x256 CTA, 64x64 warp tiles, 2-stage (n-fast grid) -------------
__device__ __forceinline__ void stage_loads_big(uint32_t sstage,
        const __nv_bfloat16* Ah, const __nv_bfloat16* Al,
        const __nv_bfloat16* Wh, const __nv_bfloat16* Wl,
        int m0, int n0, int k0, int K, int tid) {
    #pragma unroll
    for (int t = 0; t < 4; t++) {
        int u = tid + (t << 8);
        int row = u >> 3, cu = u & 7;
        cp16(sstage + swzoff(row, cu), Ah + (size_t)(m0 + row) * K + k0 + cu * 8);
    }
    #pragma unroll
    for (int t = 0; t < 4; t++) {
        int u = tid + (t << 8);
        int row = u >> 3, cu = u & 7;
        cp16(sstage + AT_BYTES + swzoff(row, cu), Al + (size_t)(m0 + row) * K + k0 + cu * 8);
    }
    #pragma unroll
    for (int t = 0; t < 8; t++) {
        int u = tid + (t << 8);
        int row = u >> 3, cu = u & 7;
        cp16(sstage + 2*AT_BYTES + swzoff(row, cu), Wh + (size_t)(n0 + row) * K + k0 + cu * 8);
    }
    #pragma unroll
    for (int t = 0; t < 8; t++) {
        int u = tid + (t << 8);
        int row = u >> 3, cu = u & 7;
        cp16(sstage + 2*AT_BYTES + BWT_BYTES + swzoff(row, cu), Wl + (size_t)(n0 + row) * K + k0 + cu * 8);
    }
    asm volatile("cp.async.commit_group;" ::: "memory");
}

__global__ void __launch_bounds__(256, 1) gemm_big_kernel(GParams p) {
    extern __shared__ char smem[];
    const int tid = threadIdx.x;
    const int wid = tid >> 5, lane = tid & 31;
    const int m0 = blockIdx.y * BMT, n0 = blockIdx.x * 256;
    const int K = p.K, N = p.N;
    const __nv_bfloat16* Wh = p.Wh[0];
    const __nv_bfloat16* Wl = p.Wl[0];
    const float* bias = p.bias[0];
    const float* res = p.res[0];
    float* C = p.C[0];
    __nv_bfloat16* Ch = p.Ch[0];
    __nv_bfloat16* Cl = p.Cl[0];
    const uint32_t sb = smem_u32(smem);

    const int wm = (wid >> 2) * 64;
    const int wn = (wid & 3) * 64;

    float acc[4][8][4];
    #pragma unroll
    for (int m = 0; m < 4; m++)
        #pragma unroll
        for (int j = 0; j < 8; j++)
            #pragma unroll
            for (int q = 0; q < 4; q++) acc[m][j][q] = 0.0f;

    const int nch = K / KC;
    stage_loads_big(sb,          p.Ah, p.Al, Wh, Wl, m0, n0, 0,  K, tid);
    stage_loads_big(sb + BSTAGE, p.Ah, p.Al, Wh, Wl, m0, n0, KC, K, tid);

    for (int i = 0; i < nch; i++) {
        asm volatile("cp.async.wait_group 1;" ::: "memory");
        __syncthreads();
        const uint32_t st = sb + (uint32_t)(i & 1) * BSTAGE;
        const uint32_t aH = st, aL = st + AT_BYTES;
        const uint32_t wH = st + 2*AT_BYTES, wL = st + 2*AT_BYTES + BWT_BYTES;

        #pragma unroll
        for (int ks = 0; ks < 4; ks++) {
            const int kbyte = ks * 32;
            uint32_t ah[4][4], al[4][4];
            #pragma unroll
            for (int m = 0; m < 4; m++) {
                ldA(ah[m], aH, wm + m * 16, kbyte, lane);
                ldA(al[m], aL, wm + m * 16, kbyte, lane);
            }
            #pragma unroll
            for (int g = 0; g < 4; g++) {
                uint32_t bh4[4], bl4[4];
                ldB(bh4, wH, wn + g * 16, kbyte, lane);
                ldB(bl4, wL, wn + g * 16, kbyte, lane);
                #pragma unroll
                for (int s = 0; s < 2; s++) {
                    int nj = g * 2 + s;
                    uint32_t h0 = bh4[s*2], h1 = bh4[s*2+1];
                    uint32_t l0 = bl4[s*2], l1 = bl4[s*2+1];
                    #pragma unroll
                    for (int m = 0; m < 4; m++) {
                        mma16816(acc[m][nj], ah[m], h0, h1);
                        mma16816(acc[m][nj], al[m], h0, h1);
                        mma16816(acc[m][nj], ah[m], l0, l1);
                    }
                }
            }
        }
        __syncthreads();
        if (i + 2 < nch)
            stage_loads_big(st, p.Ah, p.Al, Wh, Wl, m0, n0, (i + 2) * KC, K, tid);
    }

    const int lrow = lane >> 2;
    const int lcol = (lane & 3) * 2;
    #pragma unroll
    for (int m = 0; m < 4; m++) {
        int row0 = m0 + wm + m * 16 + lrow;
        int row1 = row0 + 8;
        #pragma unroll
        for (int nj = 0; nj < 8; nj++) {
            int col = n0 + wn + nj * 8 + lcol;
            epi_frag(p.act, bias, res, C, Ch, Cl, acc[m][nj][0], acc[m][nj][1],
                     acc[m][nj][2], acc[m][nj][3], row0, row1, col, N);
        }
    }
}

// ---------------- embedding + positional encoding ----------------
__global__ void embed_kernel(const int* __restrict__ x, const float* __restrict__ emb,
                             float* __restrict__ h) {
    int idx = blockIdx.x * blockDim.x + threadIdx.x;
    int d  = idx & (DD - 1);
    int bs = idx >> 10;
    int s  = bs & (SS - 1);
    int tok = x[bs];
    int i2 = d & ~1;
    float div = expf(-(float)i2 * (logf(10000.0f) / (float)DD));
    float ang = (float)s * div;
    float pe = (d & 1) ? cosf(ang) : sinf(ang);
    h[idx] = emb[(size_t)tok * DD + d] * 32.0f + pe;
}

// ---------------- layernorm (writes bf16 hi/lo split) ----------------
__global__ void __launch_bounds__(256) ln_kernel(const float* __restrict__ in,
                                                 const float* __restrict__ w,
                                                 const float* __restrict__ b,
                                                 __nv_bfloat16* __restrict__ oh,
                                                 __nv_bfloat16* __restrict__ ol) {
    int row = blockIdx.x;
    int t = threadIdx.x;
    int lane = t & 31, wid = t >> 5;
    __shared__ float red[8];

    float4 x4 = ((const float4*)(in + (size_t)row * DD))[t];
    float s = x4.x + x4.y + x4.z + x4.w;
    #pragma unroll
    for (int o = 16; o; o >>= 1) s += __shfl_xor_sync(0xffffffffu, s, o);
    if (lane == 0) red[wid] = s;
    __syncthreads();
    float tot = red[0]+red[1]+red[2]+red[3]+red[4]+red[5]+red[6]+red[7];
    float mean = tot * (1.0f / DD);
    __syncthreads();

    float d0 = x4.x - mean, d1 = x4.y - mean, d2 = x4.z - mean, d3 = x4.w - mean;
    float vs = d0*d0 + d1*d1 + d2*d2 + d3*d3;
    #pragma unroll
    for (int o = 16; o; o >>= 1) vs += __shfl_xor_sync(0xffffffffu, vs, o);
    if (lane == 0) red[wid] = vs;
    __syncthreads();
    float var = (red[0]+red[1]+red[2]+red[3]+red[4]+red[5]+red[6]+red[7]) * (1.0f / DD);
    float inv = rsqrtf(var + 1e-5f);

    float4 w4 = ((const float4*)w)[t];
    float4 b4 = ((const float4*)b)[t];
    float o0 = d0 * inv * w4.x + b4.x;
    float o1 = d1 * inv * w4.y + b4.y;
    float o2 = d2 * inv * w4.z + b4.z;
    float o3 = d3 * inv * w4.w + b4.w;
    __nv_bfloat162 H0 = split_hi2(o0, o1), H1 = split_hi2(o2, o3);
    __nv_bfloat162 L0 = split_lo2(o0, o1, H0), L1 = split_lo2(o2, o3, H1);
    ((__nv_bfloat162*)(oh + (size_t)row * DD))[2*t]   = H0;
    ((__nv_bfloat162*)(oh + (size_t)row * DD))[2*t+1] = H1;
    ((__nv_bfloat162*)(ol + (size_t)row * DD))[2*t]   = L0;
    ((__nv_bfloat162*)(ol + (size_t)row * DD))[2*t+1] = L1;
}

// ---------------- tensor-core flash attention, double-buffered K/V pipeline ----------------
__device__ __forceinline__ void att_stage(uint32_t dst, const __nv_bfloat16* src,
                                          size_t gbase, int tid) {
    #pragma unroll
    for (int t = 0; t < 4; t++) {
        int u = tid + t * 128;
        int row = u >> 3, cu = u & 7;
        cp16(dst + swzoff(row, cu), src + gbase + (size_t)row * DD + cu * 8);
    }
}
__device__ __forceinline__ void att_stage_kv(uint32_t st,
        const __nv_bfloat16* kh, const __nv_bfloat16* kl,
        const __nv_bfloat16* vh, const __nv_bfloat16* vl,
        size_t gbase, int tid) {
    att_stage(st + AK_H, kh, gbase, tid);
    att_stage(st + AK_L, kl, gbase, tid);
    att_stage(st + AV_H, vh, gbase, tid);
    att_stage(st + AV_L, vl, gbase, tid);
    asm volatile("cp.async.commit_group;" ::: "memory");
}

__global__ void __launch_bounds__(128) attn_kernel(
        const __nv_bfloat16* __restrict__ qh, const __nv_bfloat16* __restrict__ ql,
        const __nv_bfloat16* __restrict__ kh, const __nv_bfloat16* __restrict__ kl,
        const __nv_bfloat16* __restrict__ vh, const __nv_bfloat16* __restrict__ vl,
        __nv_bfloat16* __restrict__ ch, __nv_bfloat16* __restrict__ cl) {
    extern __shared__ char asmem[];
    const uint32_t sb = smem_u32(asmem);
    const int qt = blockIdx.x;
    const int bh = blockIdx.y;
    const int hh = bh & (HH - 1);
    const int bb = bh >> 4;
    const int q0 = qt * 64;

    const int tid = threadIdx.x;
    const int wid = tid >> 5, lane = tid & 31;
    const int wq = wid * 16;

    const size_t hbase = (size_t)bb * SS * DD + (size_t)hh * DK;

    // prologue: Q hi/lo staged into stage-1 area (reused by tile 1 later)
    const size_t qbase = hbase + (size_t)q0 * DD;
    att_stage(sb + AST_BYTES + AK_H, qh, qbase, tid);
    att_stage(sb + AST_BYTES + AK_L, ql, qbase, tid);
    asm volatile("cp.async.commit_group;" ::: "memory");
    // K/V tile 0 into stage 0
    att_stage_kv(sb, kh, kl, vh, vl, hbase, tid);

    // wait Q (one group may remain pending), pull Q fragments into registers
    asm volatile("cp.async.wait_group 1;" ::: "memory");
    __syncthreads();
    uint32_t qhr[4][4], qlr[4][4];
    #pragma unroll
    for (int ks = 0; ks < 4; ks++) {
        ldA(qhr[ks], sb + AST_BYTES + AK_H, wq, ks * 32, lane);
        ldA(qlr[ks], sb + AST_BYTES + AK_L, wq, ks * 32, lane);
    }

    float m0 = -1e30f, m1 = -1e30f, l0s = 0.0f, l1s = 0.0f;
    float ctx[8][4];
    #pragma unroll
    for (int j = 0; j < 8; j++)
        #pragma unroll
        for (int e = 0; e < 4; e++) ctx[j][e] = 0.0f;

    const int r = lane >> 2;
    const int cb = (lane & 3) * 2;

    const int ntiles = qt + 1;
    for (int t = 0; t < ntiles; t++) {
        asm volatile("cp.async.wait_group 0;" ::: "memory");   // tile t K/V arrived
        __syncthreads();   // publish loads; all threads done with t-1 (and Q frag reads)
        if (t + 1 < ntiles)   // prefetch next tile into the other stage
            att_stage_kv(sb + (uint32_t)((t + 1) & 1) * AST_BYTES,
                         kh, kl, vh, vl, hbase + (size_t)(t + 1) * 64 * DD, tid);
        const uint32_t st = sb + (uint32_t)(t & 1) * AST_BYTES;

        // ---- scores: S = (Qh*Kh + Ql*Kh + Qh*Kl) * 0.125 ----
        float sc[8][4];
        #pragma unroll
        for (int j = 0; j < 8; j++)
            #pragma unroll
            for (int e = 0; e < 4; e++) sc[j][e] = 0.0f;

        #pragma unroll
        for (int ks = 0; ks < 4; ks++) {
            const int kb = ks * 32;
            #pragma unroll
            for (int g = 0; g < 4; g++) {
                uint32_t khf[4], klf[4];
                ldB(khf, st + AK_H, g * 16, kb, lane);
                ldB(klf, st + AK_L, g * 16, kb, lane);
                #pragma unroll
                for (int s = 0; s < 2; s++) {
                    int nj = g * 2 + s;
                    mma16816(sc[nj], qhr[ks], khf[s*2], khf[s*2+1]);
                    mma16816(sc[nj], qlr[ks], khf[s*2], khf[s*2+1]);
                    mma16816(sc[nj], qhr[ks], klf[s*2], klf[s*2+1]);
                }
            }
        }
        #pragma unroll
        for (int nj = 0; nj < 8; nj++) {
            sc[nj][0] *= 0.125f; sc[nj][1] *= 0.125f;
            sc[nj][2] *= 0.125f; sc[nj][3] *= 0.125f;
        }

        if (t == qt) {
            #pragma unroll
            for (int nj = 0; nj < 8; nj++) {
                int c0 = nj * 8 + cb;
                if (c0     > wq + r)     sc[nj][0] = -1e30f;
                if (c0 + 1 > wq + r)     sc[nj][1] = -1e30f;
                if (c0     > wq + r + 8) sc[nj][2] = -1e30f;
                if (c0 + 1 > wq + r + 8) sc[nj][3] = -1e30f;
            }
        }

        float tm0 = -1e30f, tm1 = -1e30f;
        #pragma unroll
        for (int nj = 0; nj < 8; nj++) {
            tm0 = fmaxf(tm0, fmaxf(sc[nj][0], sc[nj][1]));
            tm1 = fmaxf(tm1, fmaxf(sc[nj][2], sc[nj][3]));
        }
        tm0 = fmaxf(tm0, __shfl_xor_sync(0xffffffffu, tm0, 1));
        tm0 = fmaxf(tm0, __shfl_xor_sync(0xffffffffu, tm0, 2));
        tm1 = fmaxf(tm1, __shfl_xor_sync(0xffffffffu, tm1, 1));
        tm1 = fmaxf(tm1, __shfl_xor_sync(0xffffffffu, tm1, 2));
        float m0n = fmaxf(m0, tm0), m1n = fmaxf(m1, tm1);
        float a0 = __expf(m0 - m0n), a1 = __expf(m1 - m1n);
        float sum0 = 0.0f, sum1 = 0.0f;
        #pragma unroll
        for (int nj = 0; nj < 8; nj++) {
            sc[nj][0] = __expf(sc[nj][0] - m0n);
            sc[nj][1] = __expf(sc[nj][1] - m0n);
            sc[nj][2] = __expf(sc[nj][2] - m1n);
            sc[nj][3] = __expf(sc[nj][3] - m1n);
            sum0 += sc[nj][0] + sc[nj][1];
            sum1 += sc[nj][2] + sc[nj][3];
        }
        sum0 += __shfl_xor_sync(0xffffffffu, sum0, 1);
        sum0 += __shfl_xor_sync(0xffffffffu, sum0, 2);
        sum1 += __shfl_xor_sync(0xffffffffu, sum1, 1);
        sum1 += __shfl_xor_sync(0xffffffffu, sum1, 2);
        l0s = l0s * a0 + sum0;
        l1s = l1s * a1 + sum1;
        m0 = m0n; m1 = m1n;
        #pragma unroll
        for (int nj = 0; nj < 8; nj++) {
            ctx[nj][0] *= a0; ctx[nj][1] *= a0;
            ctx[nj][2] *= a1; ctx[nj][3] *= a1;
        }

        // ---- PV: ctx += Ph*Vh + Ph*Vl + Pl*Vh (V via ldmatrix.trans) ----
        #pragma unroll
        for (int ks = 0; ks < 4; ks++) {
            uint32_t ph[4], pl[4];
            {
                __nv_bfloat162 t0 = split_hi2(sc[2*ks][0],   sc[2*ks][1]);
                __nv_bfloat162 t1 = split_hi2(sc[2*ks][2],   sc[2*ks][3]);
                __nv_bfloat162 t2 = split_hi2(sc[2*ks+1][0], sc[2*ks+1][1]);
                __nv_bfloat162 t3 = split_hi2(sc[2*ks+1][2], sc[2*ks+1][3]);
                ph[0] = *(uint32_t*)&t0; ph[1] = *(uint32_t*)&t1;
                ph[2] = *(uint32_t*)&t2; ph[3] = *(uint32_t*)&t3;
                __nv_bfloat162 u0 = split_lo2(sc[2*ks][0],   sc[2*ks][1],   t0);
                __nv_bfloat162 u1 = split_lo2(sc[2*ks][2],   sc[2*ks][3],   t1);
                __nv_bfloat162 u2 = split_lo2(sc[2*ks+1][0], sc[2*ks+1][1], t2);
                __nv_bfloat162 u3 = split_lo2(sc[2*ks+1][2], sc[2*ks+1][3], t3);
                pl[0] = *(uint32_t*)&u0; pl[1] = *(uint32_t*)&u1;
                pl[2] = *(uint32_t*)&u2; pl[3] = *(uint32_t*)&u3;
            }
            const int kr0 = ks * 16;
            #pragma unroll
            for (int g = 0; g < 4; g++) {
                uint32_t vhf[4], vlf[4];
                ldBt(vhf, st + AV_H, g * 16, kr0, lane);
                ldBt(vlf, st + AV_L, g * 16, kr0, lane);
                #pragma unroll
                for (int s = 0; s < 2; s++) {
                    int nj = g * 2 + s;
                    mma16816(ctx[nj], ph, vhf[s*2], vhf[s*2+1]);
                    mma16816(ctx[nj], ph, vlf[s*2], vlf[s*2+1]);
                    mma16816(ctx[nj], pl, vhf[s*2], vhf[s*2+1]);
                }
            }
        }
    }

    float i0 = 1.0f / l0s, i1 = 1.0f / l1s;
    size_t row0 = (size_t)(bb * SS + q0 + wq + r) * DD + hh * DK;
    size_t row1 = row0 + (size_t)8 * DD;
    #pragma unroll
    for (int nj = 0; nj < 8; nj++) {
        int d = nj * 8 + cb;
        float x0 = ctx[nj][0] * i0, x1 = ctx[nj][1] * i0;
        __nv_bfloat162 H = split_hi2(x0, x1);
        __nv_bfloat162 L = split_lo2(x0, x1, H);
        *(__nv_bfloat162*)(ch + row0 + d) = H;
        *(__nv_bfloat162*)(cl + row0 + d) = L;
        float y0 = ctx[nj][2] * i1, y1 = ctx[nj][3] * i1;
        __nv_bfloat162 H1 = split_hi2(y0, y1);
        __nv_bfloat162 L1 = split_lo2(y0, y1, H1);
        *(__nv_bfloat162*)(ch + row1 + d) = H1;
        *(__nv_bfloat162*)(cl + row1 + d) = L1;
    }
}

// ---------------- host-side launch helpers ----------------
static void launch_split_s(const float* x, __nv_bfloat16* h, __nv_bfloat16* l,
                           size_t n, cudaStream_t s) {
    split_kernel<<<(unsigned)(n / 4 / 256), 256, 0, s>>>(x, h, l);
}

static void launch_gemm1(const __nv_bfloat16* Ah, const __nv_bfloat16* Al,
                         const __nv_bfloat16* Wh, const __nv_bfloat16* Wl,
                         const float* bias, const float* res, float* C,
                         __nv_bfloat16* Ch, __nv_bfloat16* Cl,
                         int K, int N, int act) {
    GParams p{};
    p.Ah = Ah; p.Al = Al;
    p.Wh[0] = Wh; p.Wl[0] = Wl; p.bias[0] = bias; p.res[0] = res; p.C[0] = C;
    p.Ch[0] = Ch; p.Cl[0] = Cl;
    p.K = K; p.N = N; p.act = act;
    dim3 grid(N / BNT, MM / BMT, 1);
    gemm_bf16_kernel<<<grid, 256, GSMEM_TOTAL>>>(p);
}

static void launch_gemm_big(const __nv_bfloat16* Ah, const __nv_bfloat16* Al,
                            const __nv_bfloat16* Wh, const __nv_bfloat16* Wl,
                            const float* bias, const float* res, float* C,
                            __nv_bfloat16* Ch, __nv_bfloat16* Cl,
                            int K, int N, int act) {
    GParams p{};
    p.Ah = Ah; p.Al = Al;
    p.Wh[0] = Wh; p.Wl[0] = Wl; p.bias[0] = bias; p.res[0] = res; p.C[0] = C;
    p.Ch[0] = Ch; p.Cl[0] = Cl;
    p.K = K; p.N = N; p.act = act;
    dim3 grid(N / 256, MM / BMT, 1);
    gemm_big_kernel<<<grid, 256, BSMEM_TOTAL>>>(p);
}

extern "C" void kernel_launch(void* const* d_in, const int* in_sizes, int n_in,
                              void* d_out, int out_size) {
    const int*   x     = (const int*)d_in[0];
    const float* emb   = (const float*)d_in[1];
    const float* ln1_w = (const float*)d_in[2];
    const float* ln1_b = (const float*)d_in[3];
    const float* wq_w  = (const float*)d_in[4];
    const float* wq_b  = (const float*)d_in[5];
    const float* wk_w  = (const float*)d_in[6];
    const float* wk_b  = (const float*)d_in[7];
    const float* wv_w  = (const float*)d_in[8];
    const float* wv_b  = (const float*)d_in[9];
    const float* wo_w  = (const float*)d_in[10];
    const float* wo_b  = (const float*)d_in[11];
    const float* ln2_w = (const float*)d_in[12];
    const float* ln2_b = (const float*)d_in[13];
    const float* w1_w  = (const float*)d_in[14];
    const float* w1_b  = (const float*)d_in[15];
    const float* w2_w  = (const float*)d_in[16];
    const float* w2_b  = (const float*)d_in[17];
    const float* lnf_w = (const float*)d_in[18];
    const float* lnf_b = (const float*)d_in[19];
    float* out = (float*)d_out;

    cudaFuncSetAttribute(gemm_bf16_kernel, cudaFuncAttributeMaxDynamicSharedMemorySize,
                         GSMEM_TOTAL);
    cudaFuncSetAttribute(gemm_big_kernel, cudaFuncAttributeMaxDynamicSharedMemorySize,
                         BSMEM_TOTAL);
    cudaFuncSetAttribute(attn_kernel, cudaFuncAttributeMaxDynamicSharedMemorySize,
                         ATT_SMEM);

    float *h;
    __nv_bfloat16 *qh, *ql, *kh, *kl, *vh, *vl;
    __nv_bfloat16 *ah, *al, *bh, *bl, *wh, *wl, *eh, *el;
    cudaGetSymbolAddress((void**)&h,  g_h);
    cudaGetSymbolAddress((void**)&qh, g_qh);
    cudaGetSymbolAddress((void**)&ql, g_ql);
    cudaGetSymbolAddress((void**)&kh, g_kh);
    cudaGetSymbolAddress((void**)&kl, g_kl);
    cudaGetSymbolAddress((void**)&vh, g_vh);
    cudaGetSymbolAddress((void**)&vl, g_vl);
    cudaGetSymbolAddress((void**)&ah, g_ah);
    cudaGetSymbolAddress((void**)&al, g_al);
    cudaGetSymbolAddress((void**)&bh, g_bh);
    cudaGetSymbolAddress((void**)&bl, g_bl);
    cudaGetSymbolAddress((void**)&wh, g_wh);
    cudaGetSymbolAddress((void**)&wl, g_wl);
    cudaGetSymbolAddress((void**)&eh, g_eh);
    cudaGetSymbolAddress((void**)&el, g_el);

    // ---- fork: ALL weight splits on the side stream ----
    cudaEventRecord(g_ss.ev0, 0);
    cudaStreamWaitEvent(g_ss.s2, g_ss.ev0, 0);
    launch_split_s(wq_w, wh + OFF_WQ, wl + OFF_WQ, (size_t)LL * DD * DD, g_ss.s2);
    launch_split_s(wk_w, wh + OFF_WK, wl + OFF_WK, (size_t)LL * DD * DD, g_ss.s2);
    launch_split_s(wv_w, wh + OFF_WV, wl + OFF_WV, (size_t)LL * DD * DD, g_ss.s2);
    cudaEventRecord(g_ss.evq, g_ss.s2);
    launch_split_s(wo_w, wh + OFF_WO, wl + OFF_WO, (size_t)LL * DD * DD, g_ss.s2);
    launch_split_s(w1_w, wh + OFF_W1, wl + OFF_W1, (size_t)LL * FFD * DD, g_ss.s2);
    launch_split_s(w2_w, wh + OFF_W2, wl + OFF_W2, (size_t)LL * DD * FFD, g_ss.s2);
    cudaEventRecord(g_ss.ev1, g_ss.s2);
    launch_split_s(emb, eh, el, (size_t)VV * DD, g_ss.s2);
    cudaEventRecord(g_ss.ev2, g_ss.s2);

    // ---- main stream: embedding + layer loop ----
    embed_kernel<<<(MM * DD) / 256, 256>>>(x, emb, h);

    for (int l = 0; l < LL; l++) {
        size_t wdd = (size_t)l * DD * DD;
        size_t wfd = (size_t)l * FFD * DD;
        ln_kernel<<<MM, 256>>>(h, ln1_w + (size_t)l * DD, ln1_b + (size_t)l * DD, ah, al);

        if (l == 0) cudaStreamWaitEvent(0, g_ss.evq, 0);   // join: qkv splits done

        {   // batched QKV gemm (3-stage BN=128) -> bf16 hi/lo outputs
            GParams p{};
            p.Ah = ah; p.Al = al;
            p.Wh[0] = wh + OFF_WQ + wdd; p.Wl[0] = wl + OFF_WQ + wdd;
            p.Wh[1] = wh + OFF_WK + wdd; p.Wl[1] = wl + OFF_WK + wdd;
            p.Wh[2] = wh + OFF_WV + wdd; p.Wl[2] = wl + OFF_WV + wdd;
            p.bias[0] = wq_b + (size_t)l * DD;
            p.bias[1] = wk_b + (size_t)l * DD;
            p.bias[2] = wv_b + (size_t)l * DD;
            p.res[0] = p.res[1] = p.res[2] = nullptr;
            p.C[0] = p.C[1] = p.C[2] = nullptr;
            p.Ch[0] = qh; p.Cl[0] = ql;
            p.Ch[1] = kh; p.Cl[1] = kl;
            p.Ch[2] = vh; p.Cl[2] = vl;
            p.K = DD; p.N = DD; p.act = 0;
            dim3 grid(DD / BNT, MM / BMT, 3);
            gemm_bf16_kernel<<<grid, 256, GSMEM_TOTAL>>>(p);
        }

        attn_kernel<<<dim3(SS / 64, BB * HH), 128, ATT_SMEM>>>(qh, ql, kh, kl, vh, vl, ah, al);

        if (l == 0) cudaStreamWaitEvent(0, g_ss.ev1, 0);   // join: wo/w1/w2 splits done

        launch_gemm1(ah, al, wh + OFF_WO + wdd, wl + OFF_WO + wdd,
                     wo_b + (size_t)l * DD, h, h, nullptr, nullptr, DD, DD, 0);

        ln_kernel<<<MM, 256>>>(h, ln2_w + (size_t)l * DD, ln2_b + (size_t)l * DD, ah, al);

        launch_gemm_big(ah, al, wh + OFF_W1 + wfd, wl + OFF_W1 + wfd,
                        w1_b + (size_t)l * FFD, nullptr, nullptr, bh, bl, DD, FFD, 1);

        launch_gemm1(bh, bl, wh + OFF_W2 + wfd, wl + OFF_W2 + wfd,
                     w2_b + (size_t)l * DD, h, h, nullptr, nullptr, FFD, DD, 0);
    }

    ln_kernel<<<MM, 256>>>(h, lnf_w, lnf_b, ah, al);

    cudaStreamWaitEvent(0, g_ss.ev2, 0);   // join: embedding split done

    launch_gemm_big(ah, al, eh, el, nullptr, nullptr, out, nullptr, nullptr, DD, VV, 0);
}

// round 15
// speedup vs baseline: 1.0369x; 1.0181x over previous
#include <cuda_runtime.h>
#include <cuda_bf16.h>
#include <math.h>
#include <stdint.h>

#define VV 32000
#define DD 1024
#define LL 6
#define HH 16
#define FFD 4096
#define SS 1024
#define BB 2
#define DK 64
#define MM (BB*SS)   // 2048 rows

// ---------------- gemm tile config (BN=128, 3-stage) ----------------
#define BMT 128
#define BNT 128
#define KC 64
#define AT_BYTES (BMT*128)
#define WT_BYTES (BNT*128)
#define STAGE_BYTES (2*AT_BYTES + 2*WT_BYTES)   // 65536
#define GSMEM_TOTAL (3*STAGE_BYTES)             // 196608

// ---------------- BIG gemm config (BN=256, 2-stage) ----------------
#define BWT_BYTES (256*128)
#define BSTAGE (2*AT_BYTES + 2*BWT_BYTES)       // 98304
#define BSMEM_TOTAL (2*BSTAGE)                  // 196608

// ---------------- HALF gemm config (BM=64 x BN=128, 2-stage, occ 2) ----------------
#define HAT_BYTES (64*128)                      // 8192
#define HSTAGE (2*HAT_BYTES + 2*WT_BYTES)       // 49152
#define HSMEM_TOTAL (2*HSTAGE)                  // 98304

// ---------------- attention smem: 2 K/V stages of 32KB ----------------
#define AST_BYTES 32768
#define AK_H 0
#define AK_L 8192
#define AV_H 16384
#define AV_L 24576
#define ATT_SMEM (2*AST_BYTES)    // 65536

// ---------------- whole-model weight split offsets (elements) ----------------
#define OFF_WQ ((size_t)0)
#define OFF_WK ((size_t)6*DD*DD)
#define OFF_WV ((size_t)12*DD*DD)
#define OFF_WO ((size_t)18*DD*DD)
#define OFF_W1 ((size_t)24*DD*DD)
#define OFF_W2 ((size_t)24*DD*DD + (size_t)6*FFD*DD)
#define WTOT   ((size_t)24*DD*DD + (size_t)12*FFD*DD)

// ---------------- scratch ----------------
__device__ float g_h[MM*DD];
__device__ __nv_bfloat16 g_qh[MM*DD];
__device__ __nv_bfloat16 g_ql[MM*DD];
__device__ __nv_bfloat16 g_kh[MM*DD];
__device__ __nv_bfloat16 g_kl[MM*DD];
__device__ __nv_bfloat16 g_vh[MM*DD];
__device__ __nv_bfloat16 g_vl[MM*DD];
__device__ __nv_bfloat16 g_ah[MM*DD];
__device__ __nv_bfloat16 g_al[MM*DD];
__device__ __nv_bfloat16 g_bh[MM*FFD];
__device__ __nv_bfloat16 g_bl[MM*FFD];
__device__ __nv_bfloat16 g_wh[WTOT];
__device__ __nv_bfloat16 g_wl[WTOT];
__device__ __nv_bfloat16 g_eh[VV*DD];
__device__ __nv_bfloat16 g_el[VV*DD];

// ---------------- side stream + events ----------------
struct SideStream {
    cudaStream_t s2;
    cudaEvent_t ev0, evq, ev1, ev2;
    SideStream() {
        cudaStreamCreate(&s2);
        cudaEventCreateWithFlags(&ev0, cudaEventDisableTiming);
        cudaEventCreateWithFlags(&evq, cudaEventDisableTiming);
        cudaEventCreateWithFlags(&ev1, cudaEventDisableTiming);
        cudaEventCreateWithFlags(&ev2, cudaEventDisableTiming);
    }
};
static SideStream g_ss;

// ---------------- helpers ----------------
__device__ __forceinline__ uint32_t smem_u32(const void* p) {
    uint32_t a;
    asm("{ .reg .u64 t; cvta.to.shared.u64 t, %1; cvt.u32.u64 %0, t; }" : "=r"(a) : "l"(p));
    return a;
}
__device__ __forceinline__ float gelu_f(float x) {
    return 0.5f * x * (1.0f + erff(x * 0.70710678118654752f));
}
__device__ __forceinline__ void cp16(uint32_t dst, const void* src) {
    asm volatile("cp.async.cg.shared.global [%0], [%1], 16;" :: "r"(dst), "l"(src));
}
__device__ __forceinline__ void ldmatrix4(uint32_t* r, uint32_t addr) {
    asm volatile("ldmatrix.sync.aligned.m8n8.x4.shared.b16 {%0,%1,%2,%3}, [%4];"
                 : "=r"(r[0]), "=r"(r[1]), "=r"(r[2]), "=r"(r[3]) : "r"(addr));
}
__device__ __forceinline__ void ldmatrix4t(uint32_t* r, uint32_t addr) {
    asm volatile("ldmatrix.sync.aligned.m8n8.x4.trans.shared.b16 {%0,%1,%2,%3}, [%4];"
                 : "=r"(r[0]), "=r"(r[1]), "=r"(r[2]), "=r"(r[3]) : "r"(addr));
}
__device__ __forceinline__ void mma16816(float* c, const uint32_t* a, uint32_t b0, uint32_t b1) {
    asm volatile("mma.sync.aligned.m16n8k16.row.col.f32.bf16.bf16.f32 "
                 "{%0,%1,%2,%3}, {%4,%5,%6,%7}, {%8,%9}, {%0,%1,%2,%3};"
                 : "+f"(c[0]), "+f"(c[1]), "+f"(c[2]), "+f"(c[3])
                 : "r"(a[0]), "r"(a[1]), "r"(a[2]), "r"(a[3]), "r"(b0), "r"(b1));
}
__device__ __forceinline__ __nv_bfloat162 split_hi2(float a, float b) {
    __nv_bfloat162 r; r.x = __float2bfloat16(a); r.y = __float2bfloat16(b); return r;
}
__device__ __forceinline__ __nv_bfloat162 split_lo2(float a, float b, __nv_bfloat162 h) {
    __nv_bfloat162 r;
    r.x = __float2bfloat16(a - __bfloat162float(h.x));
    r.y = __float2bfloat16(b - __bfloat162float(h.y));
    return r;
}
__device__ __forceinline__ uint32_t swzoff(int row, int cu) {
    return (uint32_t)(row * 128 + ((cu * 16) ^ ((row & 7) * 16)));
}

// ---------------- fp32 -> (bf16 hi, bf16 lo) split ----------------
__global__ void split_kernel(const float* __restrict__ x,
                             __nv_bfloat16* __restrict__ h,
                             __nv_bfloat16* __restrict__ l) {
    int i = blockIdx.x * blockDim.x + threadIdx.x;
    float4 v = ((const float4*)x)[i];
    __nv_bfloat162 h0 = split_hi2(v.x, v.y);
    __nv_bfloat162 h1 = split_hi2(v.z, v.w);
    __nv_bfloat162 l0 = split_lo2(v.x, v.y, h0);
    __nv_bfloat162 l1 = split_lo2(v.z, v.w, h1);
    ((__nv_bfloat162*)h)[2*i]   = h0;
    ((__nv_bfloat162*)h)[2*i+1] = h1;
    ((__nv_bfloat162*)l)[2*i]   = l0;
    ((__nv_bfloat162*)l)[2*i+1] = l1;
}

// ---------------- shared GEMM param struct ----------------
struct GParams {
    const __nv_bfloat16 *Ah, *Al;
    const __nv_bfloat16 *Wh[3], *Wl[3];
    const float *bias[3];
    const float *res[3];
    float *C[3];
    __nv_bfloat16 *Ch[3], *Cl[3];
    int K, N, act;
};

__device__ __forceinline__ void ldA(uint32_t* r, uint32_t base, int r0, int kbyte, int lane) {
    int row = r0 + (lane & 15);
    int x = ((lane >> 4) * 16 + kbyte) ^ ((row & 7) * 16);
    ldmatrix4(r, base + row * 128 + x);
}
__device__ __forceinline__ void ldB(uint32_t* r, uint32_t base, int nb, int kbyte, int lane) {
    int nrow = nb + (lane & 7) + ((lane >> 4) << 3);
    int x = (((lane >> 3) & 1) * 16 + kbyte) ^ ((nrow & 7) * 16);
    ldmatrix4(r, base + nrow * 128 + x);
}
__device__ __forceinline__ void ldBt(uint32_t* r, uint32_t base, int nb, int kr0, int lane) {
    int row = kr0 + (lane & 7) + (((lane >> 3) & 1) << 3);
    int colb = nb * 2 + ((lane >> 4) << 4);
    int x = colb ^ ((row & 7) * 16);
    ldmatrix4t(r, base + row * 128 + x);
}

__device__ __forceinline__ void epi_frag(int act, const float* bias, const float* res,
        float* C, __nv_bfloat16* Ch, __nv_bfloat16* Cl,
        float a0, float a1, float a2, float a3,
        int row0, int row1, int col, int N) {
    float v00 = a0, v01 = a1, v10 = a2, v11 = a3;
    if (bias) {
        float2 b2 = *(const float2*)(bias + col);
        v00 += b2.x; v01 += b2.y; v10 += b2.x; v11 += b2.y;
    }
    if (res) {
        float2 r0 = *(const float2*)(res + (size_t)row0 * N + col);
        float2 r1 = *(const float2*)(res + (size_t)row1 * N + col);
        v00 += r0.x; v01 += r0.y; v10 += r1.x; v11 += r1.y;
    }
    if (act) {
        v00 = gelu_f(v00); v01 = gelu_f(v01);
        v10 = gelu_f(v10); v11 = gelu_f(v11);
    }
    if (Ch) {
        __nv_bfloat162 H0 = split_hi2(v00, v01);
        __nv_bfloat162 H1 = split_hi2(v10, v11);
        __nv_bfloat162 L0 = split_lo2(v00, v01, H0);
        __nv_bfloat162 L1 = split_lo2(v10, v11, H1);
        *(__nv_bfloat162*)(Ch + (size_t)row0 * N + col) = H0;
        *(__nv_bfloat162*)(Cl + (size_t)row0 * N + col) = L0;
        *(__nv_bfloat162*)(Ch + (size_t)row1 * N + col) = H1;
        *(__nv_bfloat162*)(Cl + (size_t)row1 * N + col) = L1;
    } else {
        *(float2*)(C + (size_t)row0 * N + col) = make_float2(v00, v01);
        *(float2*)(C + (size_t)row1 * N + col) = make_float2(v10, v11);
    }
}

// ---------------- 3-stage GEMM (BN=128) ----------------
__device__ __forceinline__ void stage_loads(uint32_t sstage,
        const __nv_bfloat16* Ah, const __nv_bfloat16* Al,
        const __nv_bfloat16* Wh, const __nv_bfloat16* Wl,
        int m0, int n0, int k0, int K, int tid) {
    #pragma unroll
    for (int t = 0; t < 4; t++) {
        int u = tid + (t << 8);
        int row = u >> 3, cu = u & 7;
        cp16(sstage + swzoff(row, cu), Ah + (size_t)(m0 + row) * K + k0 + cu * 8);
    }
    #pragma unroll
    for (int t = 0; t < 4; t++) {
        int u = tid + (t << 8);
        int row = u >> 3, cu = u & 7;
        cp16(sstage + AT_BYTES + swzoff(row, cu), Al + (size_t)(m0 + row) * K + k0 + cu * 8);
    }
    #pragma unroll
    for (int t = 0; t < 4; t++) {
        int u = tid + (t << 8);
        int row = u >> 3, cu = u & 7;
        cp16(sstage + 2*AT_BYTES + swzoff(row, cu), Wh + (size_t)(n0 + row) * K + k0 + cu * 8);
    }
    #pragma unroll
    for (int t = 0; t < 4; t++) {
        int u = tid + (t << 8);
        int row = u >> 3, cu = u & 7;
        cp16(sstage + 2*AT_BYTES + WT_BYTES + swzoff(row, cu), Wl + (size_t)(n0 + row) * K + k0 + cu * 8);
    }
    asm volatile("cp.async.commit_group;" ::: "memory");
}

__global__ void __launch_bounds__(256, 1) gemm_bf16_kernel(GParams p) {
    extern __shared__ char smem[];
    const int tid = threadIdx.x;
    const int wid = tid >> 5, lane = tid & 31;
    const int z = blockIdx.z;
    const int m0 = blockIdx.y * BMT, n0 = blockIdx.x * BNT;
    const int K = p.K, N = p.N;
    const __nv_bfloat16* Wh = p.Wh[z];
    const __nv_bfloat16* Wl = p.Wl[z];
    const float* bias = p.bias[z];
    const float* res = p.res[z];
    float* C = p.C[z];
    __nv_bfloat16* Ch = p.Ch[z];
    __nv_bfloat16* Cl = p.Cl[z];
    const uint32_t sb = smem_u32(smem);

    const int wm = (wid >> 1) * 32;
    const int wn = (wid & 1) * 64;

    float acc[2][8][4];
    #pragma unroll
    for (int i = 0; i < 2; i++)
        #pragma unroll
        for (int j = 0; j < 8; j++)
            #pragma unroll
            for (int q = 0; q < 4; q++) acc[i][j][q] = 0.0f;

    const int nch = K / KC;
    stage_loads(sb,                 p.Ah, p.Al, Wh, Wl, m0, n0, 0,    K, tid);
    stage_loads(sb +   STAGE_BYTES, p.Ah, p.Al, Wh, Wl, m0, n0, KC,   K, tid);
    stage_loads(sb + 2*STAGE_BYTES, p.Ah, p.Al, Wh, Wl, m0, n0, 2*KC, K, tid);

    for (int i = 0; i < nch; i++) {
        asm volatile("cp.async.wait_group 2;" ::: "memory");
        __syncthreads();
        uint32_t st = sb + (uint32_t)(i % 3) * STAGE_BYTES;
        uint32_t aH = st, aL = st + AT_BYTES;
        uint32_t wH = st + 2*AT_BYTES, wL = st + 2*AT_BYTES + WT_BYTES;

        #pragma unroll
        for (int ks = 0; ks < 4; ks++) {
            const int kbyte = ks * 32;
            uint32_t ah0[4], ah1[4], al0[4], al1[4];
            ldA(ah0, aH, wm,      kbyte, lane);
            ldA(ah1, aH, wm + 16, kbyte, lane);
            ldA(al0, aL, wm,      kbyte, lane);
            ldA(al1, aL, wm + 16, kbyte, lane);
            uint32_t bh[4][4], bl[4][4];
            #pragma unroll
            for (int g = 0; g < 4; g++) {
                ldB(bh[g], wH, wn + g * 16, kbyte, lane);
                ldB(bl[g], wL, wn + g * 16, kbyte, lane);
            }
            #pragma unroll
            for (int g = 0; g < 4; g++) {
                #pragma unroll
                for (int s = 0; s < 2; s++) {
                    int nj = g * 2 + s;
                    uint32_t h0 = bh[g][s*2], h1 = bh[g][s*2+1];
                    uint32_t l0 = bl[g][s*2], l1 = bl[g][s*2+1];
                    mma16816(acc[0][nj], ah0, h0, h1);
                    mma16816(acc[1][nj], ah1, h0, h1);
                    mma16816(acc[0][nj], al0, h0, h1);
                    mma16816(acc[1][nj], al1, h0, h1);
                    mma16816(acc[0][nj], ah0, l0, l1);
                    mma16816(acc[1][nj], ah1, l0, l1);
                }
            }
        }
        __syncthreads();
        if (i + 3 < nch)
            stage_loads(st, p.Ah, p.Al, Wh, Wl, m0, n0, (i + 3) * KC, K, tid);
    }

    const int lrow = lane >> 2;
    const int lcol = (lane & 3) * 2;
    #pragma unroll
    for (int mi = 0; mi < 2; mi++) {
        int row0 = m0 + wm + mi * 16 + lrow;
        int row1 = row0 + 8;
        #pragma unroll
        for (int nj = 0; nj < 8; nj++) {
            int col = n0 + wn + nj * 8 + lcol;
            epi_frag(p.act, bias, res, C, Ch, Cl, acc[mi][nj][0], acc[mi][nj][1],
                     acc[mi][nj][2], acc[mi][nj][3], row0, row1, col, N);
        }
    }
}

// ---------------- BIG GEMM: 128x256 CTA, 2-stage (n-fast grid) ----------------
__device__ __forceinline__ void stage_loads_big(uint32_t sstage,
        const __nv_bfloat16* Ah, const __nv_bfloat16* Al,
        const __nv_bfloat16* Wh, const __nv_bfloat16* Wl,
        int m0, int n0, int k0, int K, int tid) {
    #pragma unroll
    for (int t = 0; t < 4; t++) {
        int u = tid + (t << 8);
        int row = u >> 3, cu = u & 7;
        cp16(sstage + swzoff(row, cu), Ah + (size_t)(m0 + row) * K + k0 + cu * 8);
    }
    #pragma unroll
    for (int t = 0; t < 4; t++) {
        int u = tid + (t << 8);
        int row = u >> 3, cu = u & 7;
        cp16(sstage + AT_BYTES + swzoff(row, cu), Al + (size_t)(m0 + row) * K + k0 + cu * 8);
    }
    #pragma unroll
    for (int t = 0; t < 8; t++) {
        int u = tid + (t << 8);
        int row = u >> 3, cu = u & 7;
        cp16(sstage + 2*AT_BYTES + swzoff(row, cu), Wh + (size_t)(n0 + row) * K + k0 + cu * 8);
    }
    #pragma unroll
    for (int t = 0; t < 8; t++) {
        int u = tid + (t << 8);
        int row = u >> 3, cu = u & 7;
        cp16(sstage + 2*AT_BYTES + BWT_BYTES + swzoff(row, cu), Wl + (size_t)(n0 + row) * K + k0 + cu * 8);
    }
    asm volatile("cp.async.commit_group;" ::: "memory");
}

__global__ void __launch_bounds__(256, 1) gemm_big_kernel(GParams p) {
    extern __shared__ char smem[];
    const int tid = threadIdx.x;
    const int wid = tid >> 5, lane = tid & 31;
    const int m0 = blockIdx.y * BMT, n0 = blockIdx.x * 256;
    const int K = p.K, N = p.N;
    const __nv_bfloat16* Wh = p.Wh[0];
    const __nv_bfloat16* Wl = p.Wl[0];
    const float* bias = p.bias[0];
    const float* res = p.res[0];
    float* C = p.C[0];
    __nv_bfloat16* Ch = p.Ch[0];
    __nv_bfloat16* Cl = p.Cl[0];
    const uint32_t sb = smem_u32(smem);

    const int wm = (wid >> 2) * 64;
    const int wn = (wid & 3) * 64;

    float acc[4][8][4];
    #pragma unroll
    for (int m = 0; m < 4; m++)
        #pragma unroll
        for (int j = 0; j < 8; j++)
            #pragma unroll
            for (int q = 0; q < 4; q++) acc[m][j][q] = 0.0f;

    const int nch = K / KC;
    stage_loads_big(sb,          p.Ah, p.Al, Wh, Wl, m0, n0, 0,  K, tid);
    stage_loads_big(sb + BSTAGE, p.Ah, p.Al, Wh, Wl, m0, n0, KC, K, tid);

    for (int i = 0; i < nch; i++) {
        asm volatile("cp.async.wait_group 1;" ::: "memory");
        __syncthreads();
        const uint32_t st = sb + (uint32_t)(i & 1) * BSTAGE;
        const uint32_t aH = st, aL = st + AT_BYTES;
        const uint32_t wH = st + 2*AT_BYTES, wL = st + 2*AT_BYTES + BWT_BYTES;

        #pragma unroll
        for (int ks = 0; ks < 4; ks++) {
            const int kbyte = ks * 32;
            uint32_t ah[4][4], al[4][4];
            #pragma unroll
            for (int m = 0; m < 4; m++) {
                ldA(ah[m], aH, wm + m * 16, kbyte, lane);
                ldA(al[m], aL, wm + m * 16, kbyte, lane);
            }
            #pragma unroll
            for (int g = 0; g < 4; g++) {
                uint32_t bh4[4], bl4[4];
                ldB(bh4, wH, wn + g * 16, kbyte, lane);
                ldB(bl4, wL, wn + g * 16, kbyte, lane);
                #pragma unroll
                for (int s = 0; s < 2; s++) {
                    int nj = g * 2 + s;
                    uint32_t h0 = bh4[s*2], h1 = bh4[s*2+1];
                    uint32_t l0 = bl4[s*2], l1 = bl4[s*2+1];
                    #pragma unroll
                    for (int m = 0; m < 4; m++) {
                        mma16816(acc[m][nj], ah[m], h0, h1);
                        mma16816(acc[m][nj], al[m], h0, h1);
                        mma16816(acc[m][nj], ah[m], l0, l1);
                    }
                }
            }
        }
        __syncthreads();
        if (i + 2 < nch)
            stage_loads_big(st, p.Ah, p.Al, Wh, Wl, m0, n0, (i + 2) * KC, K, tid);
    }

    const int lrow = lane >> 2;
    const int lcol = (lane & 3) * 2;
    #pragma unroll
    for (int m = 0; m < 4; m++) {
        int row0 = m0 + wm + m * 16 + lrow;
        int row1 = row0 + 8;
        #pragma unroll
        for (int nj = 0; nj < 8; nj++) {
            int col = n0 + wn + nj * 8 + lcol;
            epi_frag(p.act, bias, res, C, Ch, Cl, acc[m][nj][0], acc[m][nj][1],
                     acc[m][nj][2], acc[m][nj][3], row0, row1, col, N);
        }
    }
}

// ---------------- HALF GEMM: 64x128 CTA, 2m x 4n warps (32x32 tiles), 2-stage, occ 2 --------
__device__ __forceinline__ void stage_loads_half(uint32_t sstage,
        const __nv_bfloat16* Ah, const __nv_bfloat16* Al,
        const __nv_bfloat16* Wh, const __nv_bfloat16* Wl,
        int m0, int n0, int k0, int K, int tid) {
    #pragma unroll
    for (int t = 0; t < 2; t++) {
        int u = tid + (t << 8);
        int row = u >> 3, cu = u & 7;
        cp16(sstage + swzoff(row, cu), Ah + (size_t)(m0 + row) * K + k0 + cu * 8);
    }
    #pragma unroll
    for (int t = 0; t < 2; t++) {
        int u = tid + (t << 8);
        int row = u >> 3, cu = u & 7;
        cp16(sstage + HAT_BYTES + swzoff(row, cu), Al + (size_t)(m0 + row) * K + k0 + cu * 8);
    }
    #pragma unroll
    for (int t = 0; t < 4; t++) {
        int u = tid + (t << 8);
        int row = u >> 3, cu = u & 7;
        cp16(sstage + 2*HAT_BYTES + swzoff(row, cu), Wh + (size_t)(n0 + row) * K + k0 + cu * 8);
    }
    #pragma unroll
    for (int t = 0; t < 4; t++) {
        int u = tid + (t << 8);
        int row = u >> 3, cu = u & 7;
        cp16(sstage + 2*HAT_BYTES + WT_BYTES + swzoff(row, cu), Wl + (size_t)(n0 + row) * K + k0 + cu * 8);
    }
    asm volatile("cp.async.commit_group;" ::: "memory");
}

__global__ void __launch_bounds__(256, 2) gemm_half_kernel(GParams p) {
    extern __shared__ char smem[];
    const int tid = threadIdx.x;
    const int wid = tid >> 5, lane = tid & 31;
    const int m0 = blockIdx.y * 64, n0 = blockIdx.x * BNT;
    const int K = p.K, N = p.N;
    const __nv_bfloat16* Wh = p.Wh[0];
    const __nv_bfloat16* Wl = p.Wl[0];
    const float* bias = p.bias[0];
    const float* res = p.res[0];
    float* C = p.C[0];
    __nv_bfloat16* Ch = p.Ch[0];
    __nv_bfloat16* Cl = p.Cl[0];
    const uint32_t sb = smem_u32(smem);

    const int wm = (wid >> 2) * 32;   // 0, 32
    const int wn = (wid & 3) * 32;    // 0, 32, 64, 96

    float acc[2][4][4];
    #pragma unroll
    for (int i = 0; i < 2; i++)
        #pragma unroll
        for (int j = 0; j < 4; j++)
            #pragma unroll
            for (int q = 0; q < 4; q++) acc[i][j][q] = 0.0f;

    const int nch = K / KC;
    stage_loads_half(sb,          p.Ah, p.Al, Wh, Wl, m0, n0, 0,  K, tid);
    stage_loads_half(sb + HSTAGE, p.Ah, p.Al, Wh, Wl, m0, n0, KC, K, tid);

    for (int i = 0; i < nch; i++) {
        asm volatile("cp.async.wait_group 1;" ::: "memory");
        __syncthreads();
        const uint32_t st = sb + (uint32_t)(i & 1) * HSTAGE;
        const uint32_t aH = st, aL = st + HAT_BYTES;
        const uint32_t wH = st + 2*HAT_BYTES, wL = st + 2*HAT_BYTES + WT_BYTES;

        #pragma unroll
        for (int ks = 0; ks < 4; ks++) {
            const int kbyte = ks * 32;
            uint32_t ah0[4], ah1[4], al0[4], al1[4];
            ldA(ah0, aH, wm,      kbyte, lane);
            ldA(ah1, aH, wm + 16, kbyte, lane);
            ldA(al0, aL, wm,      kbyte, lane);
            ldA(al1, aL, wm + 16, kbyte, lane);
            #pragma unroll
            for (int g = 0; g < 2; g++) {
                uint32_t bh4[4], bl4[4];
                ldB(bh4, wH, wn + g * 16, kbyte, lane);
                ldB(bl4, wL, wn + g * 16, kbyte, lane);
                #pragma unroll
                for (int s = 0; s < 2; s++) {
                    int nj = g * 2 + s;
                    uint32_t h0 = bh4[s*2], h1 = bh4[s*2+1];
                    uint32_t l0 = bl4[s*2], l1 = bl4[s*2+1];
                    mma16816(acc[0][nj], ah0, h0, h1);
                    mma16816(acc[1][nj], ah1, h0, h1);
                    mma16816(acc[0][nj], al0, h0, h1);
                    mma16816(acc[1][nj], al1, h0, h1);
                    mma16816(acc[0][nj], ah0, l0, l1);
                    mma16816(acc[1][nj], ah1, l0, l1);
                }
            }
        }
        __syncthreads();
        if (i + 2 < nch)
            stage_loads_half(st, p.Ah, p.Al, Wh, Wl, m0, n0, (i + 2) * KC, K, tid);
    }

    const int lrow = lane >> 2;
    const int lcol = (lane & 3) * 2;
    #pragma unroll
    for (int mi = 0; mi < 2; mi++) {
        int row0 = m0 + wm + mi * 16 + lrow;
        int row1 = row0 + 8;
        #pragma unroll
        for (int nj = 0; nj < 4; nj++) {
            int col = n0 + wn + nj * 8 + lcol;
            epi_frag(p.act, bias, res, C, Ch, Cl, acc[mi][nj][0], acc[mi][nj][1],
                     acc[mi][nj][2], acc[mi][nj][3], row0, row1, col, N);
        }
    }
}

// ---------------- embedding + positional encoding ----------------
__global__ void embed_kernel(const int* __restrict__ x, const float* __restrict__ emb,
                             float* __restrict__ h) {
    int idx = blockIdx.x * blockDim.x + threadIdx.x;
    int d  = idx & (DD - 1);
    int bs = idx >> 10;
    int s  = bs & (SS - 1);
    int tok = x[bs];
    int i2 = d & ~1;
    float div = expf(-(float)i2 * (logf(10000.0f) / (float)DD));
    float ang = (float)s * div;
    float pe = (d & 1) ? cosf(ang) : sinf(ang);
    h[idx] = emb[(size_t)tok * DD + d] * 32.0f + pe;
}

// ---------------- layernorm (writes bf16 hi/lo split) ----------------
__global__ void __launch_bounds__(256) ln_kernel(const float* __restrict__ in,
                                                 const float* __restrict__ w,
                                                 const float* __restrict__ b,
                                                 __nv_bfloat16* __restrict__ oh,
                                                 __nv_bfloat16* __restrict__ ol) {
    int row = blockIdx.x;
    int t = threadIdx.x;
    int lane = t & 31, wid = t >> 5;
    __shared__ float red[8];

    float4 x4 = ((const float4*)(in + (size_t)row * DD))[t];
    float s = x4.x + x4.y + x4.z + x4.w;
    #pragma unroll
    for (int o = 16; o; o >>= 1) s += __shfl_xor_sync(0xffffffffu, s, o);
    if (lane == 0) red[wid] = s;
    __syncthreads();
    float tot = red[0]+red[1]+red[2]+red[3]+red[4]+red[5]+red[6]+red[7];
    float mean = tot * (1.0f / DD);
    __syncthreads();

    float d0 = x4.x - mean, d1 = x4.y - mean, d2 = x4.z - mean, d3 = x4.w - mean;
    float vs = d0*d0 + d1*d1 + d2*d2 + d3*d3;
    #pragma unroll
    for (int o = 16; o; o >>= 1) vs += __shfl_xor_sync(0xffffffffu, vs, o);
    if (lane == 0) red[wid] = vs;
    __syncthreads();
    float var = (red[0]+red[1]+red[2]+red[3]+red[4]+red[5]+red[6]+red[7]) * (1.0f / DD);
    float inv = rsqrtf(var + 1e-5f);

    float4 w4 = ((const float4*)w)[t];
    float4 b4 = ((const float4*)b)[t];
    float o0 = d0 * inv * w4.x + b4.x;
    float o1 = d1 * inv * w4.y + b4.y;
    float o2 = d2 * inv * w4.z + b4.z;
    float o3 = d3 * inv * w4.w + b4.w;
    __nv_bfloat162 H0 = split_hi2(o0, o1), H1 = split_hi2(o2, o3);
    __nv_bfloat162 L0 = split_lo2(o0, o1, H0), L1 = split_lo2(o2, o3, H1);
    ((__nv_bfloat162*)(oh + (size_t)row * DD))[2*t]   = H0;
    ((__nv_bfloat162*)(oh + (size_t)row * DD))[2*t+1] = H1;
    ((__nv_bfloat162*)(ol + (size_t)row * DD))[2*t]   = L0;
    ((__nv_bfloat162*)(ol + (size_t)row * DD))[2*t+1] = L1;
}

// ---------------- tensor-core flash attention, double-buffered K/V pipeline ----------------
__device__ __forceinline__ void att_stage(uint32_t dst, const __nv_bfloat16* src,
                                          size_t gbase, int tid) {
    #pragma unroll
    for (int t = 0; t < 4; t++) {
        int u = tid + t * 128;
        int row = u >> 3, cu = u & 7;
        cp16(dst + swzoff(row, cu), src + gbase + (size_t)row * DD + cu * 8);
    }
}
__device__ __forceinline__ void att_stage_kv(uint32_t st,
        const __nv_bfloat16* kh, const __nv_bfloat16* kl,
        const __nv_bfloat16* vh, const __nv_bfloat16* vl,
        size_t gbase, int tid) {
    att_stage(st + AK_H, kh, gbase, tid);
    att_stage(st + AK_L, kl, gbase, tid);
    att_stage(st + AV_H, vh, gbase, tid);
    att_stage(st + AV_L, vl, gbase, tid);
    asm volatile("cp.async.commit_group;" ::: "memory");
}

__global__ void __launch_bounds__(128) attn_kernel(
        const __nv_bfloat16* __restrict__ qh, const __nv_bfloat16* __restrict__ ql,
        const __nv_bfloat16* __restrict__ kh, const __nv_bfloat16* __restrict__ kl,
        const __nv_bfloat16* __restrict__ vh, const __nv_bfloat16* __restrict__ vl,
        __nv_bfloat16* __restrict__ ch, __nv_bfloat16* __restrict__ cl) {
    extern __shared__ char asmem[];
    const uint32_t sb = smem_u32(asmem);
    const int qt = blockIdx.x;
    const int bh = blockIdx.y;
    const int hh = bh & (HH - 1);
    const int bb = bh >> 4;
    const int q0 = qt * 64;

    const int tid = threadIdx.x;
    const int wid = tid >> 5, lane = tid & 31;
    const int wq = wid * 16;

    const size_t hbase = (size_t)bb * SS * DD + (size_t)hh * DK;

    const size_t qbase = hbase + (size_t)q0 * DD;
    att_stage(sb + AST_BYTES + AK_H, qh, qbase, tid);
    att_stage(sb + AST_BYTES + AK_L, ql, qbase, tid);
    asm volatile("cp.async.commit_group;" ::: "memory");
    att_stage_kv(sb, kh, kl, vh, vl, hbase, tid);

    asm volatile("cp.async.wait_group 1;" ::: "memory");
    __syncthreads();
    uint32_t qhr[4][4], qlr[4][4];
    #pragma unroll
    for (int ks = 0; ks < 4; ks++) {
        ldA(qhr[ks], sb + AST_BYTES + AK_H, wq, ks * 32, lane);
        ldA(qlr[ks], sb + AST_BYTES + AK_L, wq, ks * 32, lane);
    }

    float m0 = -1e30f, m1 = -1e30f, l0s = 0.0f, l1s = 0.0f;
    float ctx[8][4];
    #pragma unroll
    for (int j = 0; j < 8; j++)
        #pragma unroll
        for (int e = 0; e < 4; e++) ctx[j][e] = 0.0f;

    const int r = lane >> 2;
    const int cb = (lane & 3) * 2;

    const int ntiles = qt + 1;
    for (int t = 0; t < ntiles; t++) {
        asm volatile("cp.async.wait_group 0;" ::: "memory");
        __syncthreads();
        if (t + 1 < ntiles)
            att_stage_kv(sb + (uint32_t)((t + 1) & 1) * AST_BYTES,
                         kh, kl, vh, vl, hbase + (size_t)(t + 1) * 64 * DD, tid);
        const uint32_t st = sb + (uint32_t)(t & 1) * AST_BYTES;

        float sc[8][4];
        #pragma unroll
        for (int j = 0; j < 8; j++)
            #pragma unroll
            for (int e = 0; e < 4; e++) sc[j][e] = 0.0f;

        #pragma unroll
        for (int ks = 0; ks < 4; ks++) {
            const int kb = ks * 32;
            #pragma unroll
            for (int g = 0; g < 4; g++) {
                uint32_t khf[4], klf[4];
                ldB(khf, st + AK_H, g * 16, kb, lane);
                ldB(klf, st + AK_L, g * 16, kb, lane);
                #pragma unroll
                for (int s = 0; s < 2; s++) {
                    int nj = g * 2 + s;
                    mma16816(sc[nj], qhr[ks], khf[s*2], khf[s*2+1]);
                    mma16816(sc[nj], qlr[ks], khf[s*2], khf[s*2+1]);
                    mma16816(sc[nj], qhr[ks], klf[s*2], klf[s*2+1]);
                }
            }
        }
        #pragma unroll
        for (int nj = 0; nj < 8; nj++) {
            sc[nj][0] *= 0.125f; sc[nj][1] *= 0.125f;
            sc[nj][2] *= 0.125f; sc[nj][3] *= 0.125f;
        }

        if (t == qt) {
            #pragma unroll
            for (int nj = 0; nj < 8; nj++) {
                int c0 = nj * 8 + cb;
                if (c0     > wq + r)     sc[nj][0] = -1e30f;
                if (c0 + 1 > wq + r)     sc[nj][1] = -1e30f;
                if (c0     > wq + r + 8) sc[nj][2] = -1e30f;
                if (c0 + 1 > wq + r + 8) sc[nj][3] = -1e30f;
            }
        }

        float tm0 = -1e30f, tm1 = -1e30f;
        #pragma unroll
        for (int nj = 0; nj < 8; nj++) {
            tm0 = fmaxf(tm0, fmaxf(sc[nj][0], sc[nj][1]));
            tm1 = fmaxf(tm1, fmaxf(sc[nj][2], sc[nj][3]));
        }
        tm0 = fmaxf(tm0, __shfl_xor_sync(0xffffffffu, tm0, 1));
        tm0 = fmaxf(tm0, __shfl_xor_sync(0xffffffffu, tm0, 2));
        tm1 = fmaxf(tm1, __shfl_xor_sync(0xffffffffu, tm1, 1));
        tm1 = fmaxf(tm1, __shfl_xor_sync(0xffffffffu, tm1, 2));
        float m0n = fmaxf(m0, tm0), m1n = fmaxf(m1, tm1);
        float a0 = __expf(m0 - m0n), a1 = __expf(m1 - m1n);
        float sum0 = 0.0f, sum1 = 0.0f;
        #pragma unroll
        for (int nj = 0; nj < 8; nj++) {
            sc[nj][0] = __expf(sc[nj][0] - m0n);
            sc[nj][1] = __expf(sc[nj][1] - m0n);
            sc[nj][2] = __expf(sc[nj][2] - m1n);
            sc[nj][3] = __expf(sc[nj][3] - m1n);
            sum0 += sc[nj][0] + sc[nj][1];
            sum1 += sc[nj][2] + sc[nj][3];
        }
        sum0 += __shfl_xor_sync(0xffffffffu, sum0, 1);
        sum0 += __shfl_xor_sync(0xffffffffu, sum0, 2);
        sum1 += __shfl_xor_sync(0xffffffffu, sum1, 1);
        sum1 += __shfl_xor_sync(0xffffffffu, sum1, 2);
        l0s = l0s * a0 + sum0;
        l1s = l1s * a1 + sum1;
        m0 = m0n; m1 = m1n;
        #pragma unroll
        for (int nj = 0; nj < 8; nj++) {
            ctx[nj][0] *= a0; ctx[nj][1] *= a0;
            ctx[nj][2] *= a1; ctx[nj][3] *= a1;
        }

        #pragma unroll
        for (int ks = 0; ks < 4; ks++) {
            uint32_t ph[4], pl[4];
            {
                __nv_bfloat162 t0 = split_hi2(sc[2*ks][0],   sc[2*ks][1]);
                __nv_bfloat162 t1 = split_hi2(sc[2*ks][2],   sc[2*ks][3]);
                __nv_bfloat162 t2 = split_hi2(sc[2*ks+1][0], sc[2*ks+1][1]);
                __nv_bfloat162 t3 = split_hi2(sc[2*ks+1][2], sc[2*ks+1][3]);
                ph[0] = *(uint32_t*)&t0; ph[1] = *(uint32_t*)&t1;
                ph[2] = *(uint32_t*)&t2; ph[3] = *(uint32_t*)&t3;
                __nv_bfloat162 u0 = split_lo2(sc[2*ks][0],   sc[2*ks][1],   t0);
                __nv_bfloat162 u1 = split_lo2(sc[2*ks][2],   sc[2*ks][3],   t1);
                __nv_bfloat162 u2 = split_lo2(sc[2*ks+1][0], sc[2*ks+1][1], t2);
                __nv_bfloat162 u3 = split_lo2(sc[2*ks+1][2], sc[2*ks+1][3], t3);
                pl[0] = *(uint32_t*)&u0; pl[1] = *(uint32_t*)&u1;
                pl[2] = *(uint32_t*)&u2; pl[3] = *(uint32_t*)&u3;
            }
            const int kr0 = ks * 16;
            #pragma unroll
            for (int g = 0; g < 4; g++) {
                uint32_t vhf[4], vlf[4];
                ldBt(vhf, st + AV_H, g * 16, kr0, lane);
                ldBt(vlf, st + AV_L, g * 16, kr0, lane);
                #pragma unroll
                for (int s = 0; s < 2; s++) {
                    int nj = g * 2 + s;
                    mma16816(ctx[nj], ph, vhf[s*2], vhf[s*2+1]);
                    mma16816(ctx[nj], ph, vlf[s*2], vlf[s*2+1]);
                    mma16816(ctx[nj], pl, vhf[s*2], vhf[s*2+1]);
                }
            }
        }
    }

    float i0 = 1.0f / l0s, i1 = 1.0f / l1s;
    size_t row0 = (size_t)(bb * SS + q0 + wq + r) * DD + hh * DK;
    size_t row1 = row0 + (size_t)8 * DD;
    #pragma unroll
    for (int nj = 0; nj < 8; nj++) {
        int d = nj * 8 + cb;
        float x0 = ctx[nj][0] * i0, x1 = ctx[nj][1] * i0;
        __nv_bfloat162 H = split_hi2(x0, x1);
        __nv_bfloat162 L = split_lo2(x0, x1, H);
        *(__nv_bfloat162*)(ch + row0 + d) = H;
        *(__nv_bfloat162*)(cl + row0 + d) = L;
        float y0 = ctx[nj][2] * i1, y1 = ctx[nj][3] * i1;
        __nv_bfloat162 H1 = split_hi2(y0, y1);
        __nv_bfloat162 L1 = split_lo2(y0, y1, H1);
        *(__nv_bfloat162*)(ch + row1 + d) = H1;
        *(__nv_bfloat162*)(cl + row1 + d) = L1;
    }
}

// ---------------- host-side launch helpers ----------------
static void launch_split_s(const float* x, __nv_bfloat16* h, __nv_bfloat16* l,
                           size_t n, cudaStream_t s) {
    split_kernel<<<(unsigned)(n / 4 / 256), 256, 0, s>>>(x, h, l);
}

static void launch_gemm_half(const __nv_bfloat16* Ah, const __nv_bfloat16* Al,
                             const __nv_bfloat16* Wh, const __nv_bfloat16* Wl,
                             const float* bias, const float* res, float* C,
                             __nv_bfloat16* Ch, __nv_bfloat16* Cl,
                             int K, int N, int act) {
    GParams p{};
    p.Ah = Ah; p.Al = Al;
    p.Wh[0] = Wh; p.Wl[0] = Wl; p.bias[0] = bias; p.res[0] = res; p.C[0] = C;
    p.Ch[0] = Ch; p.Cl[0] = Cl;
    p.K = K; p.N = N; p.act = act;
    dim3 grid(N / BNT, MM / 64, 1);
    gemm_half_kernel<<<grid, 256, HSMEM_TOTAL>>>(p);
}

static void launch_gemm_big(const __nv_bfloat16* Ah, const __nv_bfloat16* Al,
                            const __nv_bfloat16* Wh, const __nv_bfloat16* Wl,
                            const float* bias, const float* res, float* C,
                            __nv_bfloat16* Ch, __nv_bfloat16* Cl,
                            int K, int N, int act) {
    GParams p{};
    p.Ah = Ah; p.Al = Al;
    p.Wh[0] = Wh; p.Wl[0] = Wl; p.bias[0] = bias; p.res[0] = res; p.C[0] = C;
    p.Ch[0] = Ch; p.Cl[0] = Cl;
    p.K = K; p.N = N; p.act = act;
    dim3 grid(N / 256, MM / BMT, 1);
    gemm_big_kernel<<<grid, 256, BSMEM_TOTAL>>>(p);
}

extern "C" void kernel_launch(void* const* d_in, const int* in_sizes, int n_in,
                              void* d_out, int out_size) {
    const int*   x     = (const int*)d_in[0];
    const float* emb   = (const float*)d_in[1];
    const float* ln1_w = (const float*)d_in[2];
    const float* ln1_b = (const float*)d_in[3];
    const float* wq_w  = (const float*)d_in[4];
    const float* wq_b  = (const float*)d_in[5];
    const float* wk_w  = (const float*)d_in[6];
    const float* wk_b  = (const float*)d_in[7];
    const float* wv_w  = (const float*)d_in[8];
    const float* wv_b  = (const float*)d_in[9];
    const float* wo_w  = (const float*)d_in[10];
    const float* wo_b  = (const float*)d_in[11];
    const float* ln2_w = (const float*)d_in[12];
    const float* ln2_b = (const float*)d_in[13];
    const float* w1_w  = (const float*)d_in[14];
    const float* w1_b  = (const float*)d_in[15];
    const float* w2_w  = (const float*)d_in[16];
    const float* w2_b  = (const float*)d_in[17];
    const float* lnf_w = (const float*)d_in[18];
    const float* lnf_b = (const float*)d_in[19];
    float* out = (float*)d_out;

    cudaFuncSetAttribute(gemm_bf16_kernel, cudaFuncAttributeMaxDynamicSharedMemorySize,
                         GSMEM_TOTAL);
    cudaFuncSetAttribute(gemm_big_kernel, cudaFuncAttributeMaxDynamicSharedMemorySize,
                         BSMEM_TOTAL);
    cudaFuncSetAttribute(gemm_half_kernel, cudaFuncAttributeMaxDynamicSharedMemorySize,
                         HSMEM_TOTAL);
    cudaFuncSetAttribute(attn_kernel, cudaFuncAttributeMaxDynamicSharedMemorySize,
                         ATT_SMEM);

    float *h;
    __nv_bfloat16 *qh, *ql, *kh, *kl, *vh, *vl;
    __nv_bfloat16 *ah, *al, *bh, *bl, *wh, *wl, *eh, *el;
    cudaGetSymbolAddress((void**)&h,  g_h);
    cudaGetSymbolAddress((void**)&qh, g_qh);
    cudaGetSymbolAddress((void**)&ql, g_ql);
    cudaGetSymbolAddress((void**)&kh, g_kh);
    cudaGetSymbolAddress((void**)&kl, g_kl);
    cudaGetSymbolAddress((void**)&vh, g_vh);
    cudaGetSymbolAddress((void**)&vl, g_vl);
    cudaGetSymbolAddress((void**)&ah, g_ah);
    cudaGetSymbolAddress((void**)&al, g_al);
    cudaGetSymbolAddress((void**)&bh, g_bh);
    cudaGetSymbolAddress((void**)&bl, g_bl);
    cudaGetSymbolAddress((void**)&wh, g_wh);
    cudaGetSymbolAddress((void**)&wl, g_wl);
    cudaGetSymbolAddress((void**)&eh, g_eh);
    cudaGetSymbolAddress((void**)&el, g_el);

    // ---- fork: ALL weight splits on the side stream ----
    cudaEventRecord(g_ss.ev0, 0);
    cudaStreamWaitEvent(g_ss.s2, g_ss.ev0, 0);
    launch_split_s(wq_w, wh + OFF_WQ, wl + OFF_WQ, (size_t)LL * DD * DD, g_ss.s2);
    launch_split_s(wk_w, wh + OFF_WK, wl + OFF_WK, (size_t)LL * DD * DD, g_ss.s2);
    launch_split_s(wv_w, wh + OFF_WV, wl + OFF_WV, (size_t)LL * DD * DD, g_ss.s2);
    cudaEventRecord(g_ss.evq, g_ss.s2);
    launch_split_s(wo_w, wh + OFF_WO, wl + OFF_WO, (size_t)LL * DD * DD, g_ss.s2);
    launch_split_s(w1_w, wh + OFF_W1, wl + OFF_W1, (size_t)LL * FFD * DD, g_ss.s2);
    launch_split_s(w2_w, wh + OFF_W2, wl + OFF_W2, (size_t)LL * DD * FFD, g_ss.s2);
    cudaEventRecord(g_ss.ev1, g_ss.s2);
    launch_split_s(emb, eh, el, (size_t)VV * DD, g_ss.s2);
    cudaEventRecord(g_ss.ev2, g_ss.s2);

    // ---- main stream: embedding + layer loop ----
    embed_kernel<<<(MM * DD) / 256, 256>>>(x, emb, h);

    for (int l = 0; l < LL; l++) {
        size_t wdd = (size_t)l * DD * DD;
        size_t wfd = (size_t)l * FFD * DD;
        ln_kernel<<<MM, 256>>>(h, ln1_w + (size_t)l * DD, ln1_b + (size_t)l * DD, ah, al);

        if (l == 0) cudaStreamWaitEvent(0, g_ss.evq, 0);

        {   // batched QKV gemm (3-stage BN=128) -> bf16 hi/lo outputs
            GParams p{};
            p.Ah = ah; p.Al = al;
            p.Wh[0] = wh + OFF_WQ + wdd; p.Wl[0] = wl + OFF_WQ + wdd;
            p.Wh[1] = wh + OFF_WK + wdd; p.Wl[1] = wl + OFF_WK + wdd;
            p.Wh[2] = wh + OFF_WV + wdd; p.Wl[2] = wl + OFF_WV + wdd;
            p.bias[0] = wq_b + (size_t)l * DD;
            p.bias[1] = wk_b + (size_t)l * DD;
            p.bias[2] = wv_b + (size_t)l * DD;
            p.res[0] = p.res[1] = p.res[2] = nullptr;
            p.C[0] = p.C[1] = p.C[2] = nullptr;
            p.Ch[0] = qh; p.Cl[0] = ql;
            p.Ch[1] = kh; p.Cl[1] = kl;
            p.Ch[2] = vh; p.Cl[2] = vl;
            p.K = DD; p.N = DD; p.act = 0;
            dim3 grid(DD / BNT, MM / BMT, 3);
            gemm_bf16_kernel<<<grid, 256, GSMEM_TOTAL>>>(p);
        }

        attn_kernel<<<dim3(SS / 64, BB * HH), 128, ATT_SMEM>>>(qh, ql, kh, kl, vh, vl, ah, al);

        if (l == 0) cudaStreamWaitEvent(0, g_ss.ev1, 0);

        // h = h + ctx @ Wo^T + bo  (HALF kernel: 256 CTAs, occ 2)
        launch_gemm_half(ah, al, wh + OFF_WO + wdd, wl + OFF_WO + wdd,
                         wo_b + (size_t)l * DD, h, h, nullptr, nullptr, DD, DD, 0);

        ln_kernel<<<MM, 256>>>(h, ln2_w + (size_t)l * DD, ln2_b + (size_t)l * DD, ah, al);

        launch_gemm_big(ah, al, wh + OFF_W1 + wfd, wl + OFF_W1 + wfd,
                        w1_b + (size_t)l * FFD, nullptr, nullptr, bh, bl, DD, FFD, 1);

        // h = h + ff @ W2^T + b2  (HALF kernel)
        launch_gemm_half(bh, bl, wh + OFF_W2 + wfd, wl + OFF_W2 + wfd,
                         w2_b + (size_t)l * DD, h, h, nullptr, nullptr, FFD, DD, 0);
    }

    ln_kernel<<<MM, 256>>>(h, lnf_w, lnf_b, ah, al);

    cudaStreamWaitEvent(0, g_ss.ev2, 0);

    launch_gemm_big(ah, al, eh, el, nullptr, nullptr, out, nullptr, nullptr, DD, VV, 0);
}